// round 5
// baseline (speedup 1.0000x reference)
#include <cuda_runtime.h>
#include <math.h>

#define FULL 0xFFFFFFFFu

#define CH_A 0.955f
#define CH_B 1.3693f
#define CH_INF 1e6f

// ---- device scratch (no allocation allowed) ----
__device__ float    g_d[16 * 512 * 512];   // distance maps (16 MB, L2-resident)
__device__ unsigned g_seed[16 * 8192];     // seed bitboards
__device__ float    g_dmax[16];
__device__ int      g_hasfg[16];
__device__ float    g_acc[50];             // [0]=focal, [1]=bnd, [2..17]=inter, [18..33]=psum, [34..49]=tsum

__global__ void k_zero() {
    int i = threadIdx.x;
    if (i < 50) g_acc[i] = 0.0f;
}

// ============================================================================
// Seed construction: one CTA per image, 512 threads. Bitboard morphology.
// ============================================================================
__global__ void k_seeds(const int* __restrict__ target) {
    extern __shared__ unsigned char smem_raw[];
    unsigned* maskb = (unsigned*)smem_raw;   // 8192 words (512 rows x 16 words)
    unsigned* hdb   = maskb + 8192;
    unsigned* heb   = hdb + 8192;
    unsigned* bdb   = heb + 8192;

    const int img  = blockIdx.x;
    const int tid  = threadIdx.x;
    const int lane = tid & 31;
    const int wid  = tid >> 5;
    const int* tg  = target + img * (512 * 512);

    int anyfg = 0;
    #pragma unroll 8
    for (int r = 0; r < 512; ++r) {
        int v = tg[r * 512 + tid];
        unsigned bits = __ballot_sync(FULL, v > 0);
        anyfg |= (v > 0);
        if (lane == 0) maskb[r * 16 + wid] = bits;
    }
    int has_fg = __syncthreads_or(anyfg);

    // horizontal dilate / erode per 32-col word
    #pragma unroll
    for (int k = 0; k < 16; ++k) {
        int i = tid + k * 512;
        int w = i & 15;
        unsigned cw  = maskb[i];
        unsigned pw  = (w > 0)  ? maskb[i - 1] : 0u;
        unsigned nw_ = (w < 15) ? maskb[i + 1] : 0u;
        unsigned ld = (cw << 1) | (pw >> 31);
        unsigned rd = (cw >> 1) | (nw_ << 31);
        hdb[i] = cw | ld | rd;
        unsigned le = (cw << 1) | ((w == 0)  ? 1u          : (pw >> 31));
        unsigned re = (cw >> 1) | ((w == 15) ? 0x80000000u : (nw_ << 31));
        heb[i] = cw & le & re;
    }
    __syncthreads();

    // vertical combine -> boundary = dil & ~ero
    unsigned anyb = 0;
    #pragma unroll
    for (int k = 0; k < 16; ++k) {
        int i = tid + k * 512;
        int r = i >> 4;
        unsigned dil = hdb[i];
        unsigned ero = heb[i];
        if (r > 0)   { dil |= hdb[i - 16]; ero &= heb[i - 16]; }
        if (r < 511) { dil |= hdb[i + 16]; ero &= heb[i + 16]; }
        unsigned bd = dil & ~ero;
        bdb[i] = bd;
        anyb |= bd;
    }
    int has_b = __syncthreads_or(anyb != 0);

    unsigned* gs = g_seed + img * 8192;
    #pragma unroll
    for (int k = 0; k < 16; ++k) {
        int i = tid + k * 512;
        gs[i] = has_b ? bdb[i] : ~maskb[i];
    }
    if (tid == 0) g_hasfg[img] = has_fg;
}

// ============================================================================
// Chamfer sweeps: ONE WARP per TWO images (latency chains interleaved).
// 16 columns per thread per image, all in registers, tilted coords u = d - A*j.
// Zero barriers in the row loop.
// ============================================================================
__global__ void __launch_bounds__(32) k_sweep() {
    extern __shared__ unsigned sb[];          // 2 * 8192 words = 64 KB
    const int img0 = blockIdx.x * 2;
    const int lane = threadIdx.x;

    // copy both seed boards to shared
    {
        const unsigned* gs = g_seed + img0 * 8192;
        #pragma unroll
        for (int k = 0; k < 128; ++k) {
            int i = (k * 32 + lane) * 4;
            *(uint4*)(sb + i) = *(const uint4*)(gs + i);
        }
    }
    __syncwarp();

    float* dimg0 = g_d + (img0 + 0) * (512 * 512);
    float* dimg1 = g_d + (img0 + 1) * (512 * 512);

    const int c0 = lane * 16;
    float sc[16], u[2][16];
    #pragma unroll
    for (int j = 0; j < 16; ++j) {
        sc[j] = -CH_A * (float)(c0 + j);   // tilted seed value: 0 - A*j
        u[0][j] = CH_INF;
        u[1][j] = CH_INF;
    }

    // ================= Pass 1: top -> bottom, left -> right =================
    for (int r = 0; r < 512; ++r) {
        #pragma unroll
        for (int im = 0; im < 2; ++im) {
            unsigned wv   = sb[im * 8192 + (r << 4) + (lane >> 1)];
            unsigned bits = wv >> ((lane & 1) << 4);
            float uL = __shfl_up_sync(FULL, u[im][15], 1); if (lane == 0)  uL = CH_INF;
            float uR = __shfl_down_sync(FULL, u[im][0], 1); if (lane == 31) uR = CH_INF;
            float v[16];
            #pragma unroll
            for (int j = 0; j < 16; ++j) {
                float left  = (j == 0)  ? uL : u[im][j - 1];
                float right = (j == 15) ? uR : u[im][j + 1];
                float a = fminf(u[im][j] + CH_A, left + (CH_B - CH_A));
                float m = fminf(a, right + (CH_B + CH_A));
                if ((bits >> j) & 1u) m = fminf(m, sc[j]);
                v[j] = m;
            }
            // in-thread inclusive prefix-min
            float s = v[0]; u[im][0] = s;
            #pragma unroll
            for (int j = 1; j < 16; ++j) { s = fminf(s, v[j]); u[im][j] = s; }
            // warp Kogge-Stone inclusive on thread totals, then exclusive shift
            float inc = s;
            #pragma unroll
            for (int o = 1; o < 32; o <<= 1) {
                float t = __shfl_up_sync(FULL, inc, o);
                if (lane >= o) inc = fminf(inc, t);
            }
            float exc = __shfl_up_sync(FULL, inc, 1);
            if (lane == 0) exc = CH_INF;
            #pragma unroll
            for (int j = 0; j < 16; ++j) u[im][j] = fminf(u[im][j], exc);
            // store tilted row
            float* row = (im ? dimg1 : dimg0) + r * 512 + c0;
            #pragma unroll
            for (int k = 0; k < 4; ++k)
                *(float4*)(row + 4 * k) = make_float4(u[im][4*k], u[im][4*k+1], u[im][4*k+2], u[im][4*k+3]);
        }
    }

    // ================= Pass 2: bottom -> top, right -> left =================
    // pass-2 tilt: u2[j] = d[j] - A*(511-j). pass-1 rows stored tilted by -A*j:
    // convert via + A*(2j-511). Output d = u2 + A*(511-j).
    float c2[16], co[16];
    #pragma unroll
    for (int j = 0; j < 16; ++j) {
        c2[j] = CH_A * (float)(2 * (c0 + j) - 511);
        co[j] = CH_A * (float)(511 - (c0 + j));
        u[0][j] = CH_INF;
        u[1][j] = CH_INF;
    }
    float nx[2][16];
    #pragma unroll
    for (int im = 0; im < 2; ++im) {
        const float* rowp = (im ? dimg1 : dimg0) + 511 * 512 + c0;
        #pragma unroll
        for (int k = 0; k < 4; ++k) {
            float4 t4 = *(const float4*)(rowp + 4 * k);
            nx[im][4*k] = t4.x; nx[im][4*k+1] = t4.y; nx[im][4*k+2] = t4.z; nx[im][4*k+3] = t4.w;
        }
    }
    float dmx[2] = {0.0f, 0.0f};
    for (int r = 511; r >= 0; --r) {
        #pragma unroll
        for (int im = 0; im < 2; ++im) {
            float uL = __shfl_up_sync(FULL, u[im][15], 1); if (lane == 0)  uL = CH_INF;
            float uR = __shfl_down_sync(FULL, u[im][0], 1); if (lane == 31) uR = CH_INF;
            float v[16];
            #pragma unroll
            for (int j = 0; j < 16; ++j) {
                float left  = (j == 0)  ? uL : u[im][j - 1];
                float right = (j == 15) ? uR : u[im][j + 1];
                float a = fminf(u[im][j] + CH_A, right + (CH_B - CH_A));  // diag flip vs pass 1
                float b = fminf(left + (CH_B + CH_A), nx[im][j] + c2[j]);
                v[j] = fminf(a, b);
            }
            // prefetch next pass-1 row (same thread wrote it; L1/L2 hit)
            if (r > 0) {
                const float* rowp = (im ? dimg1 : dimg0) + (r - 1) * 512 + c0;
                #pragma unroll
                for (int k = 0; k < 4; ++k) {
                    float4 t4 = *(const float4*)(rowp + 4 * k);
                    nx[im][4*k] = t4.x; nx[im][4*k+1] = t4.y; nx[im][4*k+2] = t4.z; nx[im][4*k+3] = t4.w;
                }
            }
            // in-thread inclusive suffix-min (right -> left)
            float s = v[15]; u[im][15] = s;
            #pragma unroll
            for (int j = 14; j >= 0; --j) { s = fminf(s, v[j]); u[im][j] = s; }
            // warp scan over lanes above
            float inc = s;
            #pragma unroll
            for (int o = 1; o < 32; o <<= 1) {
                float t = __shfl_down_sync(FULL, inc, o);
                if (lane + o < 32) inc = fminf(inc, t);
            }
            float exc = __shfl_down_sync(FULL, inc, 1);
            if (lane == 31) exc = CH_INF;
            float out[16];
            #pragma unroll
            for (int j = 0; j < 16; ++j) {
                float uu = fminf(u[im][j], exc);
                u[im][j] = uu;
                float d = uu + co[j];           // untilt -> final distance
                out[j] = d;
                dmx[im] = fmaxf(dmx[im], d);
            }
            float* row = (im ? dimg1 : dimg0) + r * 512 + c0;
            #pragma unroll
            for (int k = 0; k < 4; ++k)
                *(float4*)(row + 4 * k) = make_float4(out[4*k], out[4*k+1], out[4*k+2], out[4*k+3]);
        }
    }

    #pragma unroll
    for (int im = 0; im < 2; ++im) {
        float m = dmx[im];
        #pragma unroll
        for (int o = 16; o >= 1; o >>= 1) m = fmaxf(m, __shfl_xor_sync(FULL, m, o));
        if (lane == 0) g_dmax[img0 + im] = m;
    }
}

// ============================================================================
// Elementwise losses + reductions. 1024 blocks x 256 threads, float4 streams.
// ============================================================================
__global__ void k_losses(const float* __restrict__ pred, const int* __restrict__ target) {
    const int img   = blockIdx.x >> 6;
    const int chunk = blockIdx.x & 63;
    const int base  = img * (512 * 512) + chunk * 4096;
    const int tid   = threadIdx.x;  // 256

    float mx  = g_dmax[img];
    float inv = (mx > 0.0f) ? (1.0f / fmaxf(mx, 1e-12f)) : 1.0f;
    int hfg   = g_hasfg[img];

    float s_focal = 0.f, s_bnd = 0.f, s_i = 0.f, s_p = 0.f, s_t = 0.f;

    #pragma unroll
    for (int k = 0; k < 4; ++k) {
        int i = base + (k * 256 + tid) * 4;
        float4 x4 = *(const float4*)(pred + i);
        int4   t4 = *(const int4*)(target + i);
        float4 d4 = *(const float4*)(g_d + i);
        #pragma unroll
        for (int e = 0; e < 4; ++e) {
            float x   = (&x4.x)[e];
            int   tgi = (&t4.x)[e];
            float dd  = (&d4.x)[e];
            float t = (float)tgi;
            float ax = fabsf(x);
            float ee = expf(-ax);
            float l  = log1pf(ee);
            float lsp = (x >= 0.f) ? -l : (x - l);       // log sigmoid(x)
            float lsn = (x >= 0.f) ? (-x - l) : -l;      // log sigmoid(-x)
            float bce = -(t * lsp + (1.f - t) * lsn);
            float p = (x >= 0.f) ? (1.f / (1.f + ee)) : (ee / (1.f + ee));
            float pt = tgi ? p : (1.f - p);
            float at = tgi ? 0.25f : 0.75f;
            float om = 1.f - pt;
            s_focal += at * om * om * bce;
            s_i += p * t;
            s_p += p;
            s_t += t;
            float dn = dd * inv;
            float dist = hfg ? dn : 1.0f;
            s_bnd += (t * (1.f - p) + (1.f - t) * p) * (1.f + dist);
        }
    }

    #pragma unroll
    for (int o = 16; o >= 1; o >>= 1) {
        s_focal += __shfl_xor_sync(FULL, s_focal, o);
        s_bnd   += __shfl_xor_sync(FULL, s_bnd, o);
        s_i     += __shfl_xor_sync(FULL, s_i, o);
        s_p     += __shfl_xor_sync(FULL, s_p, o);
        s_t     += __shfl_xor_sync(FULL, s_t, o);
    }
    __shared__ float red[8][5];
    int lane = tid & 31, wid = tid >> 5;
    if (lane == 0) { red[wid][0]=s_focal; red[wid][1]=s_bnd; red[wid][2]=s_i; red[wid][3]=s_p; red[wid][4]=s_t; }
    __syncthreads();
    if (tid == 0) {
        float a0=0,a1=0,a2=0,a3=0,a4=0;
        #pragma unroll
        for (int k = 0; k < 8; ++k) { a0+=red[k][0]; a1+=red[k][1]; a2+=red[k][2]; a3+=red[k][3]; a4+=red[k][4]; }
        atomicAdd(&g_acc[0], a0);
        atomicAdd(&g_acc[1], a1);
        atomicAdd(&g_acc[2 + img], a2);
        atomicAdd(&g_acc[18 + img], a3);
        atomicAdd(&g_acc[34 + img], a4);
    }
}

// ============================================================================
// Final combine
// ============================================================================
__global__ void k_final(const float* __restrict__ log_vars, float* __restrict__ out) {
    if (threadIdx.x != 0) return;
    const float N = 16.0f * 512.0f * 512.0f;
    float focal = g_acc[0] / N;
    float bnd   = g_acc[1] / N;
    float dsum = 0.f, isum = 0.f;
    #pragma unroll
    for (int b = 0; b < 16; ++b) {
        float I = g_acc[2 + b];
        float T = g_acc[18 + b] + g_acc[34 + b];
        dsum += (2.0f * I + 1e-6f) / (T + 1e-6f);
        isum += (I + 1e-6f) / (T - I + 1e-6f);
    }
    float dice = 1.0f - dsum / 16.0f;
    float iou  = 1.0f - isum / 16.0f;
    float lv0 = log_vars[0], lv1 = log_vars[1], lv2 = log_vars[2], lv3 = log_vars[3];
    float total = expf(-lv0) * focal + lv0
                + expf(-lv1) * dice  + lv1
                + expf(-lv2) * bnd   + lv2
                + expf(-lv3) * iou   + lv3;
    out[0] = total; out[1] = focal; out[2] = dice; out[3] = bnd; out[4] = iou;
}

extern "C" void kernel_launch(void* const* d_in, const int* in_sizes, int n_in,
                              void* d_out, int out_size) {
    const float* pred     = (const float*)d_in[0];
    const int*   target   = (const int*)d_in[1];
    const float* log_vars = (const float*)d_in[2];
    float* out = (float*)d_out;

    const size_t smem_seeds = 4 * 8192 * sizeof(unsigned);
    const size_t smem_sweep = 2 * 8192 * sizeof(unsigned);
    cudaFuncSetAttribute(k_seeds, cudaFuncAttributeMaxDynamicSharedMemorySize, (int)smem_seeds);
    cudaFuncSetAttribute(k_sweep, cudaFuncAttributeMaxDynamicSharedMemorySize, (int)smem_sweep);

    k_zero<<<1, 64>>>();
    k_seeds<<<16, 512, smem_seeds>>>(target);
    k_sweep<<<8, 32, smem_sweep>>>();
    k_losses<<<1024, 256>>>(pred, target);
    k_final<<<1, 32>>>(log_vars, out);
}

// round 6
// speedup vs baseline: 1.1469x; 1.1469x over previous
#include <cuda_runtime.h>
#include <math.h>

#define FULL 0xFFFFFFFFu

#define CH_A 0.955f
#define CH_B 1.3693f
#define CH_INF 1e6f

// ---- device scratch (no allocation allowed) ----
__device__ float    g_d[16 * 512 * 512];   // distance maps (16 MB, L2-resident)
__device__ unsigned g_seed[16 * 8192];     // seed bitboards
__device__ float    g_dmax[16];
__device__ int      g_hasfg[16];
__device__ float    g_acc[50];             // [0]=focal, [1]=bnd, [2..17]=inter, [18..33]=psum, [34..49]=tsum

__global__ void k_zero() {
    int i = threadIdx.x;
    if (i < 50) g_acc[i] = 0.0f;
}

// ============================================================================
// Seed construction: one CTA per image, 512 threads. Bitboard morphology.
// ============================================================================
__global__ void k_seeds(const int* __restrict__ target) {
    extern __shared__ unsigned char smem_raw[];
    unsigned* maskb = (unsigned*)smem_raw;   // 8192 words (512 rows x 16 words)
    unsigned* hdb   = maskb + 8192;
    unsigned* heb   = hdb + 8192;
    unsigned* bdb   = heb + 8192;

    const int img  = blockIdx.x;
    const int tid  = threadIdx.x;
    const int lane = tid & 31;
    const int wid  = tid >> 5;
    const int* tg  = target + img * (512 * 512);

    int anyfg = 0;
    #pragma unroll 8
    for (int r = 0; r < 512; ++r) {
        int v = tg[r * 512 + tid];
        unsigned bits = __ballot_sync(FULL, v > 0);
        anyfg |= (v > 0);
        if (lane == 0) maskb[r * 16 + wid] = bits;
    }
    int has_fg = __syncthreads_or(anyfg);

    #pragma unroll
    for (int k = 0; k < 16; ++k) {
        int i = tid + k * 512;
        int w = i & 15;
        unsigned cw  = maskb[i];
        unsigned pw  = (w > 0)  ? maskb[i - 1] : 0u;
        unsigned nw_ = (w < 15) ? maskb[i + 1] : 0u;
        unsigned ld = (cw << 1) | (pw >> 31);
        unsigned rd = (cw >> 1) | (nw_ << 31);
        hdb[i] = cw | ld | rd;
        unsigned le = (cw << 1) | ((w == 0)  ? 1u          : (pw >> 31));
        unsigned re = (cw >> 1) | ((w == 15) ? 0x80000000u : (nw_ << 31));
        heb[i] = cw & le & re;
    }
    __syncthreads();

    unsigned anyb = 0;
    #pragma unroll
    for (int k = 0; k < 16; ++k) {
        int i = tid + k * 512;
        int r = i >> 4;
        unsigned dil = hdb[i];
        unsigned ero = heb[i];
        if (r > 0)   { dil |= hdb[i - 16]; ero &= heb[i - 16]; }
        if (r < 511) { dil |= hdb[i + 16]; ero &= heb[i + 16]; }
        unsigned bd = dil & ~ero;
        bdb[i] = bd;
        anyb |= bd;
    }
    int has_b = __syncthreads_or(anyb != 0);

    unsigned* gs = g_seed + img * 8192;
    #pragma unroll
    for (int k = 0; k < 16; ++k) {
        int i = tid + k * 512;
        gs[i] = has_b ? bdb[i] : ~maskb[i];
    }
    if (tid == 0) g_hasfg[img] = has_fg;
}

// radix-4 helpers: inclusive min-scan over lanes (low->high), then exclusive.
// returns exclusive prefix min (INF for lane 0).
static __device__ __forceinline__ float excl_scan_min_up(float s, int lane) {
    float x = s;
    float t1 = __shfl_up_sync(FULL, x, 1);  t1 = (lane >= 1)  ? t1 : CH_INF;
    float t2 = __shfl_up_sync(FULL, x, 2);  t2 = (lane >= 2)  ? t2 : CH_INF;
    float t3 = __shfl_up_sync(FULL, x, 3);  t3 = (lane >= 3)  ? t3 : CH_INF;
    x = fminf(fminf(x, t1), fminf(t2, t3));
    float t4  = __shfl_up_sync(FULL, x, 4);  t4  = (lane >= 4)  ? t4  : CH_INF;
    float t8  = __shfl_up_sync(FULL, x, 8);  t8  = (lane >= 8)  ? t8  : CH_INF;
    float t12 = __shfl_up_sync(FULL, x, 12); t12 = (lane >= 12) ? t12 : CH_INF;
    x = fminf(fminf(x, t4), fminf(t8, t12));
    float t16 = __shfl_up_sync(FULL, x, 16);
    if (lane >= 16) x = fminf(x, t16);
    float exc = __shfl_up_sync(FULL, x, 1);
    return (lane >= 1) ? exc : CH_INF;
}

static __device__ __forceinline__ float excl_scan_min_down(float s, int lane) {
    float x = s;
    float t1 = __shfl_down_sync(FULL, x, 1);  t1 = (lane <= 30) ? t1 : CH_INF;
    float t2 = __shfl_down_sync(FULL, x, 2);  t2 = (lane <= 29) ? t2 : CH_INF;
    float t3 = __shfl_down_sync(FULL, x, 3);  t3 = (lane <= 28) ? t3 : CH_INF;
    x = fminf(fminf(x, t1), fminf(t2, t3));
    float t4  = __shfl_down_sync(FULL, x, 4);  t4  = (lane <= 27) ? t4  : CH_INF;
    float t8  = __shfl_down_sync(FULL, x, 8);  t8  = (lane <= 23) ? t8  : CH_INF;
    float t12 = __shfl_down_sync(FULL, x, 12); t12 = (lane <= 19) ? t12 : CH_INF;
    x = fminf(fminf(x, t4), fminf(t8, t12));
    float t16 = __shfl_down_sync(FULL, x, 16);
    if (lane < 16) x = fminf(x, t16);
    float exc = __shfl_down_sync(FULL, x, 1);
    return (lane <= 30) ? exc : CH_INF;
}

// ============================================================================
// Chamfer sweeps: one warp per image, 16 cols/thread in registers, tilted
// coords. Monotonicity shortcut keeps the 15-deep prefix OFF the critical
// path; seed/nx terms prefetched one row ahead.
// ============================================================================
__global__ void __launch_bounds__(32) k_sweep() {
    __shared__ unsigned sb[8192];
    const int img  = blockIdx.x;
    const int lane = threadIdx.x;
    const unsigned* gs = g_seed + img * 8192;
    float* dimg = g_d + img * (512 * 512);

    #pragma unroll
    for (int k = 0; k < 64; ++k) {
        int i = (k * 32 + lane) * 4;
        *(uint4*)(sb + i) = *(const uint4*)(gs + i);
    }
    __syncwarp();

    const int c0 = lane * 16;
    float sc[16], u[16];
    #pragma unroll
    for (int j = 0; j < 16; ++j) {
        sc[j] = -CH_A * (float)(c0 + j);   // tilted seed value: 0 - A*j
        u[j]  = CH_INF;
    }

    // prefetch row 0 seeds
    unsigned bits = (sb[(lane >> 1)] >> ((lane & 1) << 4)) & 0xFFFFu;
    float smn = bits ? (-CH_A * (float)(c0 + 31 - __clz(bits))) : CH_INF;

    // ================= Pass 1: top -> bottom, left -> right =================
    for (int r = 0; r < 512; ++r) {
        const unsigned bits_c = bits;
        const float    smn_c  = smn;
        if (r < 511) {  // prefetch next row's seed term (off-chain)
            unsigned wv = sb[((r + 1) << 4) + (lane >> 1)];
            bits = (wv >> ((lane & 1) << 4)) & 0xFFFFu;
            smn  = bits ? (-CH_A * (float)(c0 + 31 - __clz(bits))) : CH_INF;
        }
        float uL = __shfl_up_sync(FULL, u[15], 1); if (lane == 0)  uL = CH_INF;
        float uR = __shfl_down_sync(FULL, u[0], 1); if (lane == 31) uR = CH_INF;
        // thread total via monotonicity (u non-increasing in j)
        float s = fminf(fminf(u[15] + CH_A, u[14] + (CH_B - CH_A)),
                        fminf(uR + (CH_B + CH_A), smn_c));
        float exc = excl_scan_min_up(s, lane);
        // per-element v + local inclusive prefix (in scan shadow)
        float v[16];
        #pragma unroll
        for (int j = 0; j < 16; ++j) {
            float left  = (j == 0)  ? uL : u[j - 1];
            float right = (j == 15) ? uR : u[j + 1];
            float m = fminf(fminf(u[j] + CH_A, left + (CH_B - CH_A)),
                            right + (CH_B + CH_A));
            float sv = ((bits_c >> j) & 1u) ? sc[j] : CH_INF;
            v[j] = fminf(m, sv);
        }
        float p = v[0]; u[0] = fminf(p, exc);
        #pragma unroll
        for (int j = 1; j < 16; ++j) { p = fminf(p, v[j]); u[j] = fminf(p, exc); }
        float* row = dimg + r * 512 + c0;
        #pragma unroll
        for (int k = 0; k < 4; ++k)
            *(float4*)(row + 4 * k) = make_float4(u[4*k], u[4*k+1], u[4*k+2], u[4*k+3]);
    }

    // ================= Pass 2: bottom -> top, right -> left =================
    // pass-1 rows stored tilted by -A*j; pass-2 tilt u2 = d - A*(511-j):
    // convert via + c2[j], c2 = A*(2j-511). Output d = u2 + co, co = A*(511-j).
    float c2[16], co[16], nxc[16];
    #pragma unroll
    for (int j = 0; j < 16; ++j) {
        c2[j] = CH_A * (float)(2 * (c0 + j) - 511);
        co[j] = CH_A * (float)(511 - (c0 + j));
    }
    // row 511 pass-1 result is still in u
    float nxmin;
    {
        float t[8];
        #pragma unroll
        for (int j = 0; j < 16; ++j) nxc[j] = u[j] + c2[j];
        #pragma unroll
        for (int j = 0; j < 8; ++j) t[j] = fminf(nxc[j], nxc[j + 8]);
        #pragma unroll
        for (int j = 0; j < 4; ++j) t[j] = fminf(t[j], t[j + 4]);
        nxmin = fminf(fminf(t[0], t[1]), fminf(t[2], t[3]));
    }
    #pragma unroll
    for (int j = 0; j < 16; ++j) u[j] = CH_INF;

    float dmx = 0.0f;
    for (int r = 511; r >= 0; --r) {
        float uL = __shfl_up_sync(FULL, u[15], 1); if (lane == 0)  uL = CH_INF;
        float uR = __shfl_down_sync(FULL, u[0], 1); if (lane == 31) uR = CH_INF;
        // thread total via monotonicity (u non-decreasing in j for suffix-min)
        float s = fminf(fminf(u[0] + CH_A, u[1] + (CH_B - CH_A)),
                        fminf(uL + (CH_B + CH_A), nxmin));
        float exc = excl_scan_min_down(s, lane);
        // per-element v (in scan shadow)
        float v[16];
        #pragma unroll
        for (int j = 0; j < 16; ++j) {
            float left  = (j == 0)  ? uL : u[j - 1];
            float right = (j == 15) ? uR : u[j + 1];
            float a = fminf(u[j] + CH_A, right + (CH_B - CH_A));  // diag flip vs pass 1
            float b = fminf(left + (CH_B + CH_A), nxc[j]);
            v[j] = fminf(a, b);
        }
        // prefetch next pass-1 row + its min (off-chain)
        if (r > 0) {
            const float* rowp = dimg + (r - 1) * 512 + c0;
            #pragma unroll
            for (int k = 0; k < 4; ++k) {
                float4 t4 = *(const float4*)(rowp + 4 * k);
                nxc[4*k]   = t4.x + c2[4*k];
                nxc[4*k+1] = t4.y + c2[4*k+1];
                nxc[4*k+2] = t4.z + c2[4*k+2];
                nxc[4*k+3] = t4.w + c2[4*k+3];
            }
            float t[8];
            #pragma unroll
            for (int j = 0; j < 8; ++j) t[j] = fminf(nxc[j], nxc[j + 8]);
            #pragma unroll
            for (int j = 0; j < 4; ++j) t[j] = fminf(t[j], t[j + 4]);
            nxmin = fminf(fminf(t[0], t[1]), fminf(t[2], t[3]));
        }
        // in-thread suffix prefix-min (right -> left) + merge + untilt
        float out[16];
        float p = v[15]; u[15] = fminf(p, exc);
        out[15] = u[15] + co[15];
        #pragma unroll
        for (int j = 14; j >= 0; --j) {
            p = fminf(p, v[j]);
            u[j] = fminf(p, exc);
            out[j] = u[j] + co[j];
        }
        // max tree (off-chain)
        float t[8];
        #pragma unroll
        for (int j = 0; j < 8; ++j) t[j] = fmaxf(out[j], out[j + 8]);
        #pragma unroll
        for (int j = 0; j < 4; ++j) t[j] = fmaxf(t[j], t[j + 4]);
        dmx = fmaxf(dmx, fmaxf(fmaxf(t[0], t[1]), fmaxf(t[2], t[3])));

        float* row = dimg + r * 512 + c0;
        #pragma unroll
        for (int k = 0; k < 4; ++k)
            *(float4*)(row + 4 * k) = make_float4(out[4*k], out[4*k+1], out[4*k+2], out[4*k+3]);
    }

    #pragma unroll
    for (int o = 16; o >= 1; o >>= 1) dmx = fmaxf(dmx, __shfl_xor_sync(FULL, dmx, o));
    if (lane == 0) g_dmax[img] = dmx;
}

// ============================================================================
// Elementwise losses + reductions. 1024 blocks x 256 threads, float4 streams.
// ============================================================================
__global__ void k_losses(const float* __restrict__ pred, const int* __restrict__ target) {
    const int img   = blockIdx.x >> 6;
    const int chunk = blockIdx.x & 63;
    const int base  = img * (512 * 512) + chunk * 4096;
    const int tid   = threadIdx.x;  // 256

    float mx  = g_dmax[img];
    float inv = (mx > 0.0f) ? (1.0f / fmaxf(mx, 1e-12f)) : 1.0f;
    int hfg   = g_hasfg[img];

    float s_focal = 0.f, s_bnd = 0.f, s_i = 0.f, s_p = 0.f, s_t = 0.f;

    #pragma unroll
    for (int k = 0; k < 4; ++k) {
        int i = base + (k * 256 + tid) * 4;
        float4 x4 = *(const float4*)(pred + i);
        int4   t4 = *(const int4*)(target + i);
        float4 d4 = *(const float4*)(g_d + i);
        #pragma unroll
        for (int e = 0; e < 4; ++e) {
            float x   = (&x4.x)[e];
            int   tgi = (&t4.x)[e];
            float dd  = (&d4.x)[e];
            float t = (float)tgi;
            float ax = fabsf(x);
            float ee = expf(-ax);
            float l  = log1pf(ee);
            float lsp = (x >= 0.f) ? -l : (x - l);       // log sigmoid(x)
            float lsn = (x >= 0.f) ? (-x - l) : -l;      // log sigmoid(-x)
            float bce = -(t * lsp + (1.f - t) * lsn);
            float p = (x >= 0.f) ? (1.f / (1.f + ee)) : (ee / (1.f + ee));
            float pt = tgi ? p : (1.f - p);
            float at = tgi ? 0.25f : 0.75f;
            float om = 1.f - pt;
            s_focal += at * om * om * bce;
            s_i += p * t;
            s_p += p;
            s_t += t;
            float dn = dd * inv;
            float dist = hfg ? dn : 1.0f;
            s_bnd += (t * (1.f - p) + (1.f - t) * p) * (1.f + dist);
        }
    }

    #pragma unroll
    for (int o = 16; o >= 1; o >>= 1) {
        s_focal += __shfl_xor_sync(FULL, s_focal, o);
        s_bnd   += __shfl_xor_sync(FULL, s_bnd, o);
        s_i     += __shfl_xor_sync(FULL, s_i, o);
        s_p     += __shfl_xor_sync(FULL, s_p, o);
        s_t     += __shfl_xor_sync(FULL, s_t, o);
    }
    __shared__ float red[8][5];
    int lane = tid & 31, wid = tid >> 5;
    if (lane == 0) { red[wid][0]=s_focal; red[wid][1]=s_bnd; red[wid][2]=s_i; red[wid][3]=s_p; red[wid][4]=s_t; }
    __syncthreads();
    if (tid == 0) {
        float a0=0,a1=0,a2=0,a3=0,a4=0;
        #pragma unroll
        for (int k = 0; k < 8; ++k) { a0+=red[k][0]; a1+=red[k][1]; a2+=red[k][2]; a3+=red[k][3]; a4+=red[k][4]; }
        atomicAdd(&g_acc[0], a0);
        atomicAdd(&g_acc[1], a1);
        atomicAdd(&g_acc[2 + img], a2);
        atomicAdd(&g_acc[18 + img], a3);
        atomicAdd(&g_acc[34 + img], a4);
    }
}

// ============================================================================
// Final combine
// ============================================================================
__global__ void k_final(const float* __restrict__ log_vars, float* __restrict__ out) {
    if (threadIdx.x != 0) return;
    const float N = 16.0f * 512.0f * 512.0f;
    float focal = g_acc[0] / N;
    float bnd   = g_acc[1] / N;
    float dsum = 0.f, isum = 0.f;
    #pragma unroll
    for (int b = 0; b < 16; ++b) {
        float I = g_acc[2 + b];
        float T = g_acc[18 + b] + g_acc[34 + b];
        dsum += (2.0f * I + 1e-6f) / (T + 1e-6f);
        isum += (I + 1e-6f) / (T - I + 1e-6f);
    }
    float dice = 1.0f - dsum / 16.0f;
    float iou  = 1.0f - isum / 16.0f;
    float lv0 = log_vars[0], lv1 = log_vars[1], lv2 = log_vars[2], lv3 = log_vars[3];
    float total = expf(-lv0) * focal + lv0
                + expf(-lv1) * dice  + lv1
                + expf(-lv2) * bnd   + lv2
                + expf(-lv3) * iou   + lv3;
    out[0] = total; out[1] = focal; out[2] = dice; out[3] = bnd; out[4] = iou;
}

extern "C" void kernel_launch(void* const* d_in, const int* in_sizes, int n_in,
                              void* d_out, int out_size) {
    const float* pred     = (const float*)d_in[0];
    const int*   target   = (const int*)d_in[1];
    const float* log_vars = (const float*)d_in[2];
    float* out = (float*)d_out;

    const size_t smem_seeds = 4 * 8192 * sizeof(unsigned);
    cudaFuncSetAttribute(k_seeds, cudaFuncAttributeMaxDynamicSharedMemorySize, (int)smem_seeds);

    k_zero<<<1, 64>>>();
    k_seeds<<<16, 512, smem_seeds>>>(target);
    k_sweep<<<16, 32>>>();
    k_losses<<<1024, 256>>>(pred, target);
    k_final<<<1, 32>>>(log_vars, out);
}

// round 7
// speedup vs baseline: 1.1777x; 1.0269x over previous
#include <cuda_runtime.h>
#include <math.h>

#define FULL 0xFFFFFFFFu

#define CH_A 0.955f
#define CH_B 1.3693f
#define CH_INF 1e6f

// ---- device scratch (no allocation allowed) ----
__device__ float    g_u[16 * 512 * 512];   // pass-1 tilted rows, then pass-2 tilted rows
__device__ float    g_F[16 * 512 * 512];   // pass-1 seed prefix term
__device__ float    g_S[16 * 512 * 512];   // pass-2 suffix term
__device__ unsigned g_seed[16 * 8192];     // seed bitboards
__device__ int      g_dmaxb[16];           // per-image max distance (float bits, >=0)
__device__ int      g_hasfg[16];
__device__ float    g_acc[50];             // [0]=focal, [1]=bnd, [2..17]=inter, [18..33]=psum, [34..49]=tsum

__global__ void k_zero() {
    int i = threadIdx.x;
    if (i < 50) g_acc[i] = 0.0f;
    if (i < 16) g_dmaxb[i] = 0;
}

// ============================================================================
// Seed construction: one CTA per image, 512 threads. Bitboard morphology.
// ============================================================================
__global__ void k_seeds(const int* __restrict__ target) {
    extern __shared__ unsigned char smem_raw[];
    unsigned* maskb = (unsigned*)smem_raw;   // 8192 words (512 rows x 16 words)
    unsigned* hdb   = maskb + 8192;
    unsigned* heb   = hdb + 8192;
    unsigned* bdb   = heb + 8192;

    const int img  = blockIdx.x;
    const int tid  = threadIdx.x;
    const int lane = tid & 31;
    const int wid  = tid >> 5;
    const int* tg  = target + img * (512 * 512);

    int anyfg = 0;
    #pragma unroll 8
    for (int r = 0; r < 512; ++r) {
        int v = tg[r * 512 + tid];
        unsigned bits = __ballot_sync(FULL, v > 0);
        anyfg |= (v > 0);
        if (lane == 0) maskb[r * 16 + wid] = bits;
    }
    int has_fg = __syncthreads_or(anyfg);

    #pragma unroll
    for (int k = 0; k < 16; ++k) {
        int i = tid + k * 512;
        int w = i & 15;
        unsigned cw  = maskb[i];
        unsigned pw  = (w > 0)  ? maskb[i - 1] : 0u;
        unsigned nw_ = (w < 15) ? maskb[i + 1] : 0u;
        unsigned ld = (cw << 1) | (pw >> 31);
        unsigned rd = (cw >> 1) | (nw_ << 31);
        hdb[i] = cw | ld | rd;
        unsigned le = (cw << 1) | ((w == 0)  ? 1u          : (pw >> 31));
        unsigned re = (cw >> 1) | ((w == 15) ? 0x80000000u : (nw_ << 31));
        heb[i] = cw & le & re;
    }
    __syncthreads();

    unsigned anyb = 0;
    #pragma unroll
    for (int k = 0; k < 16; ++k) {
        int i = tid + k * 512;
        int r = i >> 4;
        unsigned dil = hdb[i];
        unsigned ero = heb[i];
        if (r > 0)   { dil |= hdb[i - 16]; ero &= heb[i - 16]; }
        if (r < 511) { dil |= hdb[i + 16]; ero &= heb[i + 16]; }
        unsigned bd = dil & ~ero;
        bdb[i] = bd;
        anyb |= bd;
    }
    int has_b = __syncthreads_or(anyb != 0);

    unsigned* gs = g_seed + img * 8192;
    #pragma unroll
    for (int k = 0; k < 16; ++k) {
        int i = tid + k * 512;
        gs[i] = has_b ? bdb[i] : ~maskb[i];
    }
    if (tid == 0) g_hasfg[img] = has_fg;
}

// ============================================================================
// F builder: F[r][j] = -A * (index of last seeded column <= j in row r), or INF.
// One CTA per image, 512 threads.
// ============================================================================
__global__ void k_prep() {
    extern __shared__ unsigned pm[];          // [0..8191] seed words, then C[512][16] ints
    int* C = (int*)(pm + 8192);
    const int img = blockIdx.x;
    const int tid = threadIdx.x;
    const unsigned* gs = g_seed + img * 8192;

    #pragma unroll
    for (int k = 0; k < 16; ++k) pm[tid + k * 512] = gs[tid + k * 512];
    __syncthreads();

    // stage 1: per-row carry table (thread = row)
    {
        int cur = -1;
        #pragma unroll
        for (int w = 0; w < 16; ++w) {
            C[tid * 16 + w] = cur;
            unsigned word = pm[tid * 16 + w];
            if (word) cur = w * 32 + 31 - __clz(word);
        }
    }
    __syncthreads();

    // stage 2: elementwise F (coalesced)
    float* Fimg = g_F + img * 262144;
    for (int idx = tid; idx < 262144; idx += 512) {
        int r = idx >> 9, j = idx & 511;
        int w = j >> 5, b = j & 31;
        unsigned word = pm[r * 16 + w];
        unsigned lb = word & (0xFFFFFFFFu >> (31 - b));
        int id = lb ? (w * 32 + 31 - __clz(lb)) : C[r * 16 + w];
        Fimg[idx] = (id >= 0) ? (-CH_A * (float)id) : CH_INF;
    }
}

// ============================================================================
// Pass 1: top->bottom. 2 warps (64 threads) per image, 8 cols/thread.
// Closed form: u'[j] = min(u[j]+A, u[j-1]+(B-A), u[j+1]+(B+A), F[j]).
// Halos via double-buffered shared; one barrier per row. Stores tilted u1.
// ============================================================================
__global__ void __launch_bounds__(64) k_sweep1() {
    __shared__ float shL[2][66], shR[2][66];
    const int img = blockIdx.x;
    const int tid = threadIdx.x;           // 0..63
    const int c0  = tid * 8;
    const float* Fimg = g_F + img * 262144;
    float* uimg = g_u + img * 262144;

    shL[0][tid] = CH_INF; shL[1][tid] = CH_INF;
    shR[0][tid] = CH_INF; shR[1][tid] = CH_INF;
    if (tid < 2) { shL[tid][64] = CH_INF; shL[tid][65] = CH_INF;
                   shR[tid][64] = CH_INF; shR[tid][65] = CH_INF; }

    float u[8];
    #pragma unroll
    for (int j = 0; j < 8; ++j) u[j] = CH_INF;

    float f[8];
    {
        float4 a = *(const float4*)(Fimg + c0);
        float4 b = *(const float4*)(Fimg + c0 + 4);
        f[0]=a.x; f[1]=a.y; f[2]=a.z; f[3]=a.w; f[4]=b.x; f[5]=b.y; f[6]=b.z; f[7]=b.w;
    }
    __syncthreads();

    int p = 0;
    for (int r = 0; r < 512; ++r) {
        float fn[8];
        if (r < 511) {
            const float* fp_ = Fimg + (r + 1) * 512 + c0;
            float4 a = *(const float4*)(fp_);
            float4 b = *(const float4*)(fp_ + 4);
            fn[0]=a.x; fn[1]=a.y; fn[2]=a.z; fn[3]=a.w; fn[4]=b.x; fn[5]=b.y; fn[6]=b.z; fn[7]=b.w;
        }
        float hL = shR[p][tid];        // u_prev[c0-1]
        float hR = shL[p][tid + 1];    // u_prev[c0+8]
        float nu[8];
        #pragma unroll
        for (int j = 0; j < 8; ++j) {
            float left  = (j == 0) ? hL : u[j - 1];
            float right = (j == 7) ? hR : u[j + 1];
            float m0 = fminf(u[j] + CH_A, left + (CH_B - CH_A));
            float m1 = fminf(right + (CH_B + CH_A), f[j]);
            nu[j] = fminf(m0, m1);
        }
        float* row = uimg + r * 512 + c0;
        *(float4*)(row)     = make_float4(nu[0], nu[1], nu[2], nu[3]);
        *(float4*)(row + 4) = make_float4(nu[4], nu[5], nu[6], nu[7]);
        shR[p ^ 1][tid + 1] = nu[7];
        shL[p ^ 1][tid]     = nu[0];
        #pragma unroll
        for (int j = 0; j < 8; ++j) { u[j] = nu[j]; f[j] = fn[j]; }
        __syncthreads();
        p ^= 1;
    }
}

// ============================================================================
// Suffix-term builder: S[r][j] = min_{k>=j} (u1[r][k] + A*(2k-511)).
// One warp per row; 8192 rows fully parallel.
// ============================================================================
__global__ void k_suffix() {
    const int gw   = (blockIdx.x * 256 + threadIdx.x) >> 5;   // row id 0..8191
    const int lane = threadIdx.x & 31;
    const int img  = gw >> 9, row = gw & 511;
    const float* u1 = g_u + img * 262144 + row * 512 + lane * 16;
    float* Sp       = g_S + img * 262144 + row * 512 + lane * 16;

    float nxc[16];
    #pragma unroll
    for (int k = 0; k < 4; ++k) {
        float4 t4 = *(const float4*)(u1 + 4 * k);
        int cb = lane * 16 + 4 * k;
        nxc[4*k]   = t4.x + CH_A * (float)(2 * (cb)     - 511);
        nxc[4*k+1] = t4.y + CH_A * (float)(2 * (cb + 1) - 511);
        nxc[4*k+2] = t4.z + CH_A * (float)(2 * (cb + 2) - 511);
        nxc[4*k+3] = t4.w + CH_A * (float)(2 * (cb + 3) - 511);
    }
    float s[16];
    s[15] = nxc[15];
    #pragma unroll
    for (int j = 14; j >= 0; --j) s[j] = fminf(s[j + 1], nxc[j]);
    float inc = s[0];
    #pragma unroll
    for (int o = 1; o < 32; o <<= 1) {
        float t = __shfl_down_sync(FULL, inc, o);
        if (lane + o < 32) inc = fminf(inc, t);
    }
    float exc = __shfl_down_sync(FULL, inc, 1);
    if (lane == 31) exc = CH_INF;
    #pragma unroll
    for (int k = 0; k < 4; ++k)
        *(float4*)(Sp + 4 * k) = make_float4(fminf(s[4*k], exc), fminf(s[4*k+1], exc),
                                             fminf(s[4*k+2], exc), fminf(s[4*k+3], exc));
}

// ============================================================================
// Pass 2: bottom->top, mirrored. u2'[j] = min(u2[j]+A, u2[j+1]+(B-A),
// u2[j-1]+(B+A), S[j]). Stores tilted u2 over g_u.
// ============================================================================
__global__ void __launch_bounds__(64) k_sweep2() {
    __shared__ float shL[2][66], shR[2][66];
    const int img = blockIdx.x;
    const int tid = threadIdx.x;
    const int c0  = tid * 8;
    const float* Simg = g_S + img * 262144;
    float* uimg = g_u + img * 262144;

    shL[0][tid] = CH_INF; shL[1][tid] = CH_INF;
    shR[0][tid] = CH_INF; shR[1][tid] = CH_INF;
    if (tid < 2) { shL[tid][64] = CH_INF; shL[tid][65] = CH_INF;
                   shR[tid][64] = CH_INF; shR[tid][65] = CH_INF; }

    float u[8];
    #pragma unroll
    for (int j = 0; j < 8; ++j) u[j] = CH_INF;

    float f[8];
    {
        const float* sp = Simg + 511 * 512 + c0;
        float4 a = *(const float4*)(sp);
        float4 b = *(const float4*)(sp + 4);
        f[0]=a.x; f[1]=a.y; f[2]=a.z; f[3]=a.w; f[4]=b.x; f[5]=b.y; f[6]=b.z; f[7]=b.w;
    }
    __syncthreads();

    int p = 0;
    for (int r = 511; r >= 0; --r) {
        float fn[8];
        if (r > 0) {
            const float* sp = Simg + (r - 1) * 512 + c0;
            float4 a = *(const float4*)(sp);
            float4 b = *(const float4*)(sp + 4);
            fn[0]=a.x; fn[1]=a.y; fn[2]=a.z; fn[3]=a.w; fn[4]=b.x; fn[5]=b.y; fn[6]=b.z; fn[7]=b.w;
        }
        float hL = shR[p][tid];
        float hR = shL[p][tid + 1];
        float nu[8];
        #pragma unroll
        for (int j = 0; j < 8; ++j) {
            float left  = (j == 0) ? hL : u[j - 1];
            float right = (j == 7) ? hR : u[j + 1];
            float m0 = fminf(u[j] + CH_A, right + (CH_B - CH_A));   // mirrored
            float m1 = fminf(left + (CH_B + CH_A), f[j]);
            nu[j] = fminf(m0, m1);
        }
        float* row = uimg + r * 512 + c0;
        *(float4*)(row)     = make_float4(nu[0], nu[1], nu[2], nu[3]);
        *(float4*)(row + 4) = make_float4(nu[4], nu[5], nu[6], nu[7]);
        shR[p ^ 1][tid + 1] = nu[7];
        shL[p ^ 1][tid]     = nu[0];
        #pragma unroll
        for (int j = 0; j < 8; ++j) { u[j] = nu[j]; f[j] = fn[j]; }
        __syncthreads();
        p ^= 1;
    }
}

// ============================================================================
// Per-image max of d = u2 + A*(511-col). atomicMax on float bits (d >= 0).
// ============================================================================
__global__ void k_dmax() {
    const int base = blockIdx.x * 4096;
    const int img  = blockIdx.x >> 6;
    const int tid  = threadIdx.x;   // 256
    float m = 0.0f;
    #pragma unroll
    for (int k = 0; k < 4; ++k) {
        int i = base + (k * 256 + tid) * 4;
        float4 u4 = *(const float4*)(g_u + i);
        int col = i & 511;
        m = fmaxf(m, u4.x + CH_A * (float)(511 - col));
        m = fmaxf(m, u4.y + CH_A * (float)(510 - col));
        m = fmaxf(m, u4.z + CH_A * (float)(509 - col));
        m = fmaxf(m, u4.w + CH_A * (float)(508 - col));
    }
    #pragma unroll
    for (int o = 16; o >= 1; o >>= 1) m = fmaxf(m, __shfl_xor_sync(FULL, m, o));
    __shared__ float red[8];
    if ((tid & 31) == 0) red[tid >> 5] = m;
    __syncthreads();
    if (tid == 0) {
        float mm = red[0];
        #pragma unroll
        for (int k = 1; k < 8; ++k) mm = fmaxf(mm, red[k]);
        atomicMax(&g_dmaxb[img], __float_as_int(mm));
    }
}

// ============================================================================
// Elementwise losses + reductions. Untilts u2 on the fly.
// ============================================================================
__global__ void k_losses(const float* __restrict__ pred, const int* __restrict__ target) {
    const int img   = blockIdx.x >> 6;
    const int chunk = blockIdx.x & 63;
    const int base  = img * (512 * 512) + chunk * 4096;
    const int tid   = threadIdx.x;  // 256

    float mx  = __int_as_float(g_dmaxb[img]);
    float inv = (mx > 0.0f) ? (1.0f / fmaxf(mx, 1e-12f)) : 1.0f;
    int hfg   = g_hasfg[img];

    float s_focal = 0.f, s_bnd = 0.f, s_i = 0.f, s_p = 0.f, s_t = 0.f;

    #pragma unroll
    for (int k = 0; k < 4; ++k) {
        int i = base + (k * 256 + tid) * 4;
        float4 x4 = *(const float4*)(pred + i);
        int4   t4 = *(const int4*)(target + i);
        float4 u4 = *(const float4*)(g_u + i);
        int col = i & 511;
        #pragma unroll
        for (int e = 0; e < 4; ++e) {
            float x   = (&x4.x)[e];
            int   tgi = (&t4.x)[e];
            float dd  = (&u4.x)[e] + CH_A * (float)(511 - col - e);
            float t = (float)tgi;
            float ax = fabsf(x);
            float ee = expf(-ax);
            float l  = log1pf(ee);
            float lsp = (x >= 0.f) ? -l : (x - l);
            float lsn = (x >= 0.f) ? (-x - l) : -l;
            float bce = -(t * lsp + (1.f - t) * lsn);
            float p = (x >= 0.f) ? (1.f / (1.f + ee)) : (ee / (1.f + ee));
            float pt = tgi ? p : (1.f - p);
            float at = tgi ? 0.25f : 0.75f;
            float om = 1.f - pt;
            s_focal += at * om * om * bce;
            s_i += p * t;
            s_p += p;
            s_t += t;
            float dn = dd * inv;
            float dist = hfg ? dn : 1.0f;
            s_bnd += (t * (1.f - p) + (1.f - t) * p) * (1.f + dist);
        }
    }

    #pragma unroll
    for (int o = 16; o >= 1; o >>= 1) {
        s_focal += __shfl_xor_sync(FULL, s_focal, o);
        s_bnd   += __shfl_xor_sync(FULL, s_bnd, o);
        s_i     += __shfl_xor_sync(FULL, s_i, o);
        s_p     += __shfl_xor_sync(FULL, s_p, o);
        s_t     += __shfl_xor_sync(FULL, s_t, o);
    }
    __shared__ float red[8][5];
    int lane = tid & 31, wid = tid >> 5;
    if (lane == 0) { red[wid][0]=s_focal; red[wid][1]=s_bnd; red[wid][2]=s_i; red[wid][3]=s_p; red[wid][4]=s_t; }
    __syncthreads();
    if (tid == 0) {
        float a0=0,a1=0,a2=0,a3=0,a4=0;
        #pragma unroll
        for (int k = 0; k < 8; ++k) { a0+=red[k][0]; a1+=red[k][1]; a2+=red[k][2]; a3+=red[k][3]; a4+=red[k][4]; }
        atomicAdd(&g_acc[0], a0);
        atomicAdd(&g_acc[1], a1);
        atomicAdd(&g_acc[2 + img], a2);
        atomicAdd(&g_acc[18 + img], a3);
        atomicAdd(&g_acc[34 + img], a4);
    }
}

// ============================================================================
// Final combine
// ============================================================================
__global__ void k_final(const float* __restrict__ log_vars, float* __restrict__ out) {
    if (threadIdx.x != 0) return;
    const float N = 16.0f * 512.0f * 512.0f;
    float focal = g_acc[0] / N;
    float bnd   = g_acc[1] / N;
    float dsum = 0.f, isum = 0.f;
    #pragma unroll
    for (int b = 0; b < 16; ++b) {
        float I = g_acc[2 + b];
        float T = g_acc[18 + b] + g_acc[34 + b];
        dsum += (2.0f * I + 1e-6f) / (T + 1e-6f);
        isum += (I + 1e-6f) / (T - I + 1e-6f);
    }
    float dice = 1.0f - dsum / 16.0f;
    float iou  = 1.0f - isum / 16.0f;
    float lv0 = log_vars[0], lv1 = log_vars[1], lv2 = log_vars[2], lv3 = log_vars[3];
    float total = expf(-lv0) * focal + lv0
                + expf(-lv1) * dice  + lv1
                + expf(-lv2) * bnd   + lv2
                + expf(-lv3) * iou   + lv3;
    out[0] = total; out[1] = focal; out[2] = dice; out[3] = bnd; out[4] = iou;
}

extern "C" void kernel_launch(void* const* d_in, const int* in_sizes, int n_in,
                              void* d_out, int out_size) {
    const float* pred     = (const float*)d_in[0];
    const int*   target   = (const int*)d_in[1];
    const float* log_vars = (const float*)d_in[2];
    float* out = (float*)d_out;

    const size_t smem_seeds = 4 * 8192 * sizeof(unsigned);
    const size_t smem_prep  = 8192 * sizeof(unsigned) + 512 * 16 * sizeof(int);
    cudaFuncSetAttribute(k_seeds, cudaFuncAttributeMaxDynamicSharedMemorySize, (int)smem_seeds);
    cudaFuncSetAttribute(k_prep,  cudaFuncAttributeMaxDynamicSharedMemorySize, (int)smem_prep);

    k_zero<<<1, 64>>>();
    k_seeds<<<16, 512, smem_seeds>>>(target);
    k_prep<<<16, 512, smem_prep>>>();
    k_sweep1<<<16, 64>>>();
    k_suffix<<<1024, 256>>>();
    k_sweep2<<<16, 64>>>();
    k_dmax<<<1024, 256>>>();
    k_losses<<<1024, 256>>>(pred, target);
    k_final<<<1, 32>>>(log_vars, out);
}

// round 8
// speedup vs baseline: 2.1311x; 1.8095x over previous
#include <cuda_runtime.h>
#include <math.h>

#define FULL 0xFFFFFFFFu

#define CH_A 0.955f
#define CH_B 1.3693f
#define CH_INF 1e6f

#define RB 64            // rows per block
#define NB 8             // blocks per image

// ---- device scratch (no allocation allowed) ----
__device__ float    g_u[16 * 512 * 512];   // pass-1 tilted rows, then pass-2 tilted rows
__device__ float    g_F[16 * 512 * 512];   // pass-1 seed prefix term
__device__ float    g_S[16 * 512 * 512];   // pass-2 suffix term
__device__ float    g_bnd[16 * NB * 512];  // corrected block-boundary rows
__device__ unsigned g_seed[16 * 8192];     // seed bitboards
__device__ int      g_dmaxb[16];           // per-image max distance (float bits, >=0)
__device__ int      g_hasfg[16];
__device__ float    g_acc[50];

__global__ void k_zero() {
    int i = threadIdx.x;
    if (i < 50) g_acc[i] = 0.0f;
    if (i < 16) g_dmaxb[i] = 0;
}

// ============================================================================
// Seed construction: one CTA per image, 512 threads. Bitboard morphology.
// ============================================================================
__global__ void k_seeds(const int* __restrict__ target) {
    extern __shared__ unsigned char smem_raw[];
    unsigned* maskb = (unsigned*)smem_raw;
    unsigned* hdb   = maskb + 8192;
    unsigned* heb   = hdb + 8192;
    unsigned* bdb   = heb + 8192;

    const int img  = blockIdx.x;
    const int tid  = threadIdx.x;
    const int lane = tid & 31;
    const int wid  = tid >> 5;
    const int* tg  = target + img * (512 * 512);

    int anyfg = 0;
    #pragma unroll 8
    for (int r = 0; r < 512; ++r) {
        int v = tg[r * 512 + tid];
        unsigned bits = __ballot_sync(FULL, v > 0);
        anyfg |= (v > 0);
        if (lane == 0) maskb[r * 16 + wid] = bits;
    }
    int has_fg = __syncthreads_or(anyfg);

    #pragma unroll
    for (int k = 0; k < 16; ++k) {
        int i = tid + k * 512;
        int w = i & 15;
        unsigned cw  = maskb[i];
        unsigned pw  = (w > 0)  ? maskb[i - 1] : 0u;
        unsigned nw_ = (w < 15) ? maskb[i + 1] : 0u;
        unsigned ld = (cw << 1) | (pw >> 31);
        unsigned rd = (cw >> 1) | (nw_ << 31);
        hdb[i] = cw | ld | rd;
        unsigned le = (cw << 1) | ((w == 0)  ? 1u          : (pw >> 31));
        unsigned re = (cw >> 1) | ((w == 15) ? 0x80000000u : (nw_ << 31));
        heb[i] = cw & le & re;
    }
    __syncthreads();

    unsigned anyb = 0;
    #pragma unroll
    for (int k = 0; k < 16; ++k) {
        int i = tid + k * 512;
        int r = i >> 4;
        unsigned dil = hdb[i];
        unsigned ero = heb[i];
        if (r > 0)   { dil |= hdb[i - 16]; ero &= heb[i - 16]; }
        if (r < 511) { dil |= hdb[i + 16]; ero &= heb[i + 16]; }
        unsigned bd = dil & ~ero;
        bdb[i] = bd;
        anyb |= bd;
    }
    int has_b = __syncthreads_or(anyb != 0);

    unsigned* gs = g_seed + img * 8192;
    #pragma unroll
    for (int k = 0; k < 16; ++k) {
        int i = tid + k * 512;
        gs[i] = has_b ? bdb[i] : ~maskb[i];
    }
    if (tid == 0) g_hasfg[img] = has_fg;
}

// ============================================================================
// F builder: F[r][j] = -A * (index of last seeded column <= j in row r), or INF.
// ============================================================================
__global__ void k_prep() {
    extern __shared__ unsigned pm[];
    int* C = (int*)(pm + 8192);
    const int img = blockIdx.x;
    const int tid = threadIdx.x;
    const unsigned* gs = g_seed + img * 8192;

    #pragma unroll
    for (int k = 0; k < 16; ++k) pm[tid + k * 512] = gs[tid + k * 512];
    __syncthreads();

    {
        int cur = -1;
        #pragma unroll
        for (int w = 0; w < 16; ++w) {
            C[tid * 16 + w] = cur;
            unsigned word = pm[tid * 16 + w];
            if (word) cur = w * 32 + 31 - __clz(word);
        }
    }
    __syncthreads();

    float* Fimg = g_F + img * 262144;
    for (int idx = tid; idx < 262144; idx += 512) {
        int r = idx >> 9, j = idx & 511;
        int w = j >> 5, b = j & 31;
        unsigned word = pm[r * 16 + w];
        unsigned lb = word & (0xFFFFFFFFu >> (31 - b));
        int id = lb ? (w * 32 + 31 - __clz(lb)) : C[r * 16 + w];
        Fimg[idx] = (id >= 0) ? (-CH_A * (float)id) : CH_INF;
    }
}

static __device__ __forceinline__ void ldrow16(float* d, const float* p) {
    float4 a = *(const float4*)(p);
    float4 b = *(const float4*)(p + 4);
    float4 c = *(const float4*)(p + 8);
    float4 e = *(const float4*)(p + 12);
    d[0]=a.x; d[1]=a.y; d[2]=a.z; d[3]=a.w;
    d[4]=b.x; d[5]=b.y; d[6]=b.z; d[7]=b.w;
    d[8]=c.x; d[9]=c.y; d[10]=c.z; d[11]=c.w;
    d[12]=e.x; d[13]=e.y; d[14]=e.z; d[15]=e.w;
}
static __device__ __forceinline__ void strow16(float* p, const float* d) {
    *(float4*)(p)      = make_float4(d[0], d[1], d[2], d[3]);
    *(float4*)(p + 4)  = make_float4(d[4], d[5], d[6], d[7]);
    *(float4*)(p + 8)  = make_float4(d[8], d[9], d[10], d[11]);
    *(float4*)(p + 12) = make_float4(d[12], d[13], d[14], d[15]);
}

// ============================================================================
// Pass-1 local sweeps: 1 warp per (image, block). 64-row closed-form recurrence
// from u=INF, shfl halos, barrier-free. Stores tilted local rows.
// ============================================================================
__global__ void __launch_bounds__(32) k_local1() {
    const int img = blockIdx.x >> 3, blk = blockIdx.x & 7;
    const int lane = threadIdx.x, c0 = lane * 16;
    const float* Fb = g_F + img * 262144 + blk * RB * 512;
    float* ub = g_u + img * 262144 + blk * RB * 512;

    float u[16], f[16], fn[16], nu[16];
    #pragma unroll
    for (int j = 0; j < 16; ++j) u[j] = CH_INF;
    ldrow16(f, Fb + c0);

    for (int r = 0; r < RB; ++r) {
        if (r < RB - 1) ldrow16(fn, Fb + (r + 1) * 512 + c0);
        float uL = __shfl_up_sync(FULL, u[15], 1); if (lane == 0)  uL = CH_INF;
        float uR = __shfl_down_sync(FULL, u[0], 1); if (lane == 31) uR = CH_INF;
        #pragma unroll
        for (int j = 0; j < 16; ++j) {
            float left  = (j == 0)  ? uL : u[j - 1];
            float right = (j == 15) ? uR : u[j + 1];
            nu[j] = fminf(fminf(u[j] + CH_A, left + (CH_B - CH_A)),
                          fminf(right + (CH_B + CH_A), f[j]));
        }
        strow16(ub + r * 512 + c0, nu);
        #pragma unroll
        for (int j = 0; j < 16; ++j) { u[j] = nu[j]; f[j] = fn[j]; }
    }
}

// ============================================================================
// Pass-1 boundary propagation: 1 CTA per image, 512 threads. Serial over
// blocks; T^64 applied via 6 doubling steps (windowed tilted min) in shared.
// ============================================================================
__global__ void k_bnd1() {
    __shared__ float bb[512], wa[512], wb[512], wc[512], wd[512];
    const int img = blockIdx.x;
    const int j = threadIdx.x;
    const float* base = g_u + img * 262144;
    float* gb = g_bnd + img * NB * 512;

    bb[j] = base[(RB - 1) * 512 + j];
    gb[j] = bb[j];
    __syncthreads();

    for (int i = 1; i < NB; ++i) {
        wa[j] = bb[j]; wc[j] = bb[j];
        __syncthreads();
        float *Wr = wa, *Wr2 = wb, *Wl = wc, *Wl2 = wd;
        #pragma unroll
        for (int l = 0; l < 6; ++l) {
            int s = 1 << l;
            Wr2[j] = fminf(Wr[j], (j >= s)      ? Wr[j - s] + (CH_B - CH_A) * (float)s : CH_INF);
            Wl2[j] = fminf(Wl[j], (j + s < 512) ? Wl[j + s] + (CH_B + CH_A) * (float)s : CH_INF);
            __syncthreads();
            float* t;
            t = Wr; Wr = Wr2; Wr2 = t;
            t = Wl; Wl = Wl2; Wl2 = t;
        }
        float corr = fminf(Wr[j], (j >= RB)       ? bb[j - RB] + (CH_B - CH_A) * (float)RB : CH_INF);
        corr = fminf(corr, fminf(Wl[j], (j + RB < 512) ? bb[j + RB] + (CH_B + CH_A) * (float)RB : CH_INF));
        corr += CH_A * (float)RB;
        float loc = base[(i * RB + RB - 1) * 512 + j];
        float nb = fminf(corr, loc);
        __syncthreads();
        bb[j] = nb;
        gb[i * 512 + j] = nb;
        __syncthreads();
    }
}

// ============================================================================
// Pass-1 fix: 1 warp per (image, block 1..7). Propagate v <- T (x) v from the
// previous block's true boundary; merge with stored local rows.
// ============================================================================
__global__ void __launch_bounds__(32) k_fix1() {
    const int img = blockIdx.x / (NB - 1);
    const int blk = blockIdx.x % (NB - 1) + 1;
    const int lane = threadIdx.x, c0 = lane * 16;
    float* ub = g_u + img * 262144 + blk * RB * 512;

    float v[16], nv[16], loc[16], locn[16];
    ldrow16(v, g_bnd + (img * NB + blk - 1) * 512 + c0);
    ldrow16(locn, ub + c0);

    for (int r = 0; r < RB; ++r) {
        #pragma unroll
        for (int j = 0; j < 16; ++j) loc[j] = locn[j];
        if (r < RB - 1) ldrow16(locn, ub + (r + 1) * 512 + c0);
        float vL = __shfl_up_sync(FULL, v[15], 1); if (lane == 0)  vL = CH_INF;
        float vR = __shfl_down_sync(FULL, v[0], 1); if (lane == 31) vR = CH_INF;
        #pragma unroll
        for (int j = 0; j < 16; ++j) {
            float left  = (j == 0)  ? vL : v[j - 1];
            float right = (j == 15) ? vR : v[j + 1];
            nv[j] = fminf(v[j] + CH_A, fminf(left + (CH_B - CH_A), right + (CH_B + CH_A)));
        }
        float out[16];
        #pragma unroll
        for (int j = 0; j < 16; ++j) out[j] = fminf(nv[j], loc[j]);
        strow16(ub + r * 512 + c0, out);
        #pragma unroll
        for (int j = 0; j < 16; ++j) v[j] = nv[j];
    }
}

// ============================================================================
// Suffix-term builder: S[r][j] = min_{k>=j} (u1[r][k] + A*(2k-511)).
// ============================================================================
__global__ void k_suffix() {
    const int gw   = (blockIdx.x * 256 + threadIdx.x) >> 5;
    const int lane = threadIdx.x & 31;
    const int img  = gw >> 9, row = gw & 511;
    const float* u1 = g_u + img * 262144 + row * 512 + lane * 16;
    float* Sp       = g_S + img * 262144 + row * 512 + lane * 16;

    float nxc[16];
    #pragma unroll
    for (int k = 0; k < 4; ++k) {
        float4 t4 = *(const float4*)(u1 + 4 * k);
        int cb = lane * 16 + 4 * k;
        nxc[4*k]   = t4.x + CH_A * (float)(2 * (cb)     - 511);
        nxc[4*k+1] = t4.y + CH_A * (float)(2 * (cb + 1) - 511);
        nxc[4*k+2] = t4.z + CH_A * (float)(2 * (cb + 2) - 511);
        nxc[4*k+3] = t4.w + CH_A * (float)(2 * (cb + 3) - 511);
    }
    float s[16];
    s[15] = nxc[15];
    #pragma unroll
    for (int j = 14; j >= 0; --j) s[j] = fminf(s[j + 1], nxc[j]);
    float inc = s[0];
    #pragma unroll
    for (int o = 1; o < 32; o <<= 1) {
        float t = __shfl_down_sync(FULL, inc, o);
        if (lane + o < 32) inc = fminf(inc, t);
    }
    float exc = __shfl_down_sync(FULL, inc, 1);
    if (lane == 31) exc = CH_INF;
    #pragma unroll
    for (int k = 0; k < 4; ++k)
        *(float4*)(Sp + 4 * k) = make_float4(fminf(s[4*k], exc), fminf(s[4*k+1], exc),
                                             fminf(s[4*k+2], exc), fminf(s[4*k+3], exc));
}

// ============================================================================
// Pass-2 local sweeps (mirrored, bottom->top within block).
// ============================================================================
__global__ void __launch_bounds__(32) k_local2() {
    const int img = blockIdx.x >> 3, blk = blockIdx.x & 7;
    const int lane = threadIdx.x, c0 = lane * 16;
    const float* Sb = g_S + img * 262144 + blk * RB * 512;
    float* ub = g_u + img * 262144 + blk * RB * 512;

    float u[16], f[16], fn[16], nu[16];
    #pragma unroll
    for (int j = 0; j < 16; ++j) u[j] = CH_INF;
    ldrow16(f, Sb + (RB - 1) * 512 + c0);

    for (int r = RB - 1; r >= 0; --r) {
        if (r > 0) ldrow16(fn, Sb + (r - 1) * 512 + c0);
        float uL = __shfl_up_sync(FULL, u[15], 1); if (lane == 0)  uL = CH_INF;
        float uR = __shfl_down_sync(FULL, u[0], 1); if (lane == 31) uR = CH_INF;
        #pragma unroll
        for (int j = 0; j < 16; ++j) {
            float left  = (j == 0)  ? uL : u[j - 1];
            float right = (j == 15) ? uR : u[j + 1];
            nu[j] = fminf(fminf(u[j] + CH_A, right + (CH_B - CH_A)),
                          fminf(left + (CH_B + CH_A), f[j]));
        }
        strow16(ub + r * 512 + c0, nu);
        #pragma unroll
        for (int j = 0; j < 16; ++j) { u[j] = nu[j]; f[j] = fn[j]; }
    }
}

// ============================================================================
// Pass-2 boundary propagation (mirrored slopes, blocks bottom-up).
// ============================================================================
__global__ void k_bnd2() {
    __shared__ float bb[512], wa[512], wb[512], wc[512], wd[512];
    const int img = blockIdx.x;
    const int j = threadIdx.x;
    const float* base = g_u + img * 262144;
    float* gb = g_bnd + img * NB * 512;

    bb[j] = base[((NB - 1) * RB) * 512 + j];
    gb[(NB - 1) * 512 + j] = bb[j];
    __syncthreads();

    for (int i = NB - 2; i >= 0; --i) {
        wa[j] = bb[j]; wc[j] = bb[j];
        __syncthreads();
        float *Wr = wa, *Wr2 = wb, *Wl = wc, *Wl2 = wd;
        #pragma unroll
        for (int l = 0; l < 6; ++l) {
            int s = 1 << l;
            Wr2[j] = fminf(Wr[j], (j + s < 512) ? Wr[j + s] + (CH_B - CH_A) * (float)s : CH_INF);
            Wl2[j] = fminf(Wl[j], (j >= s)      ? Wl[j - s] + (CH_B + CH_A) * (float)s : CH_INF);
            __syncthreads();
            float* t;
            t = Wr; Wr = Wr2; Wr2 = t;
            t = Wl; Wl = Wl2; Wl2 = t;
        }
        float corr = fminf(Wr[j], (j + RB < 512) ? bb[j + RB] + (CH_B - CH_A) * (float)RB : CH_INF);
        corr = fminf(corr, fminf(Wl[j], (j >= RB) ? bb[j - RB] + (CH_B + CH_A) * (float)RB : CH_INF));
        corr += CH_A * (float)RB;
        float loc = base[(i * RB) * 512 + j];
        float nb = fminf(corr, loc);
        __syncthreads();
        bb[j] = nb;
        gb[i * 512 + j] = nb;
        __syncthreads();
    }
}

// ============================================================================
// Pass-2 fix: blocks 0..6, v from boundary of block i+1, rows top of block
// downward in index (r = RB-1 .. 0).
// ============================================================================
__global__ void __launch_bounds__(32) k_fix2() {
    const int img = blockIdx.x / (NB - 1);
    const int blk = blockIdx.x % (NB - 1);          // 0..6
    const int lane = threadIdx.x, c0 = lane * 16;
    float* ub = g_u + img * 262144 + blk * RB * 512;

    float v[16], nv[16], loc[16], locn[16];
    ldrow16(v, g_bnd + (img * NB + blk + 1) * 512 + c0);
    ldrow16(locn, ub + (RB - 1) * 512 + c0);

    for (int r = RB - 1; r >= 0; --r) {
        #pragma unroll
        for (int j = 0; j < 16; ++j) loc[j] = locn[j];
        if (r > 0) ldrow16(locn, ub + (r - 1) * 512 + c0);
        float vL = __shfl_up_sync(FULL, v[15], 1); if (lane == 0)  vL = CH_INF;
        float vR = __shfl_down_sync(FULL, v[0], 1); if (lane == 31) vR = CH_INF;
        #pragma unroll
        for (int j = 0; j < 16; ++j) {
            float left  = (j == 0)  ? vL : v[j - 1];
            float right = (j == 15) ? vR : v[j + 1];
            nv[j] = fminf(v[j] + CH_A, fminf(right + (CH_B - CH_A), left + (CH_B + CH_A)));
        }
        float out[16];
        #pragma unroll
        for (int j = 0; j < 16; ++j) out[j] = fminf(nv[j], loc[j]);
        strow16(ub + r * 512 + c0, out);
        #pragma unroll
        for (int j = 0; j < 16; ++j) v[j] = nv[j];
    }
}

// ============================================================================
// Per-image max of d = u2 + A*(511-col).
// ============================================================================
__global__ void k_dmax() {
    const int base = blockIdx.x * 4096;
    const int img  = blockIdx.x >> 6;
    const int tid  = threadIdx.x;
    float m = 0.0f;
    #pragma unroll
    for (int k = 0; k < 4; ++k) {
        int i = base + (k * 256 + tid) * 4;
        float4 u4 = *(const float4*)(g_u + i);
        int col = i & 511;
        m = fmaxf(m, u4.x + CH_A * (float)(511 - col));
        m = fmaxf(m, u4.y + CH_A * (float)(510 - col));
        m = fmaxf(m, u4.z + CH_A * (float)(509 - col));
        m = fmaxf(m, u4.w + CH_A * (float)(508 - col));
    }
    #pragma unroll
    for (int o = 16; o >= 1; o >>= 1) m = fmaxf(m, __shfl_xor_sync(FULL, m, o));
    __shared__ float red[8];
    if ((tid & 31) == 0) red[tid >> 5] = m;
    __syncthreads();
    if (tid == 0) {
        float mm = red[0];
        #pragma unroll
        for (int k = 1; k < 8; ++k) mm = fmaxf(mm, red[k]);
        atomicMax(&g_dmaxb[img], __float_as_int(mm));
    }
}

// ============================================================================
// Elementwise losses + reductions (untilts u2 on the fly). 2048 blocks.
// ============================================================================
__global__ void k_losses(const float* __restrict__ pred, const int* __restrict__ target) {
    const int img   = blockIdx.x >> 7;
    const int chunk = blockIdx.x & 127;
    const int base  = img * (512 * 512) + chunk * 2048;
    const int tid   = threadIdx.x;  // 256

    float mx  = __int_as_float(g_dmaxb[img]);
    float inv = (mx > 0.0f) ? (1.0f / fmaxf(mx, 1e-12f)) : 1.0f;
    int hfg   = g_hasfg[img];

    float s_focal = 0.f, s_bnd = 0.f, s_i = 0.f, s_p = 0.f, s_t = 0.f;

    #pragma unroll
    for (int k = 0; k < 2; ++k) {
        int i = base + (k * 256 + tid) * 4;
        float4 x4 = *(const float4*)(pred + i);
        int4   t4 = *(const int4*)(target + i);
        float4 u4 = *(const float4*)(g_u + i);
        int col = i & 511;
        #pragma unroll
        for (int e = 0; e < 4; ++e) {
            float x   = (&x4.x)[e];
            int   tgi = (&t4.x)[e];
            float dd  = (&u4.x)[e] + CH_A * (float)(511 - col - e);
            float t = (float)tgi;
            float ax = fabsf(x);
            float ee = expf(-ax);
            float l  = log1pf(ee);
            float lsp = (x >= 0.f) ? -l : (x - l);
            float lsn = (x >= 0.f) ? (-x - l) : -l;
            float bce = -(t * lsp + (1.f - t) * lsn);
            float p = (x >= 0.f) ? (1.f / (1.f + ee)) : (ee / (1.f + ee));
            float pt = tgi ? p : (1.f - p);
            float at = tgi ? 0.25f : 0.75f;
            float om = 1.f - pt;
            s_focal += at * om * om * bce;
            s_i += p * t;
            s_p += p;
            s_t += t;
            float dn = dd * inv;
            float dist = hfg ? dn : 1.0f;
            s_bnd += (t * (1.f - p) + (1.f - t) * p) * (1.f + dist);
        }
    }

    #pragma unroll
    for (int o = 16; o >= 1; o >>= 1) {
        s_focal += __shfl_xor_sync(FULL, s_focal, o);
        s_bnd   += __shfl_xor_sync(FULL, s_bnd, o);
        s_i     += __shfl_xor_sync(FULL, s_i, o);
        s_p     += __shfl_xor_sync(FULL, s_p, o);
        s_t     += __shfl_xor_sync(FULL, s_t, o);
    }
    __shared__ float red[8][5];
    int lane = tid & 31, wid = tid >> 5;
    if (lane == 0) { red[wid][0]=s_focal; red[wid][1]=s_bnd; red[wid][2]=s_i; red[wid][3]=s_p; red[wid][4]=s_t; }
    __syncthreads();
    if (tid == 0) {
        float a0=0,a1=0,a2=0,a3=0,a4=0;
        #pragma unroll
        for (int k = 0; k < 8; ++k) { a0+=red[k][0]; a1+=red[k][1]; a2+=red[k][2]; a3+=red[k][3]; a4+=red[k][4]; }
        atomicAdd(&g_acc[0], a0);
        atomicAdd(&g_acc[1], a1);
        atomicAdd(&g_acc[2 + img], a2);
        atomicAdd(&g_acc[18 + img], a3);
        atomicAdd(&g_acc[34 + img], a4);
    }
}

// ============================================================================
// Final combine
// ============================================================================
__global__ void k_final(const float* __restrict__ log_vars, float* __restrict__ out) {
    if (threadIdx.x != 0) return;
    const float N = 16.0f * 512.0f * 512.0f;
    float focal = g_acc[0] / N;
    float bnd   = g_acc[1] / N;
    float dsum = 0.f, isum = 0.f;
    #pragma unroll
    for (int b = 0; b < 16; ++b) {
        float I = g_acc[2 + b];
        float T = g_acc[18 + b] + g_acc[34 + b];
        dsum += (2.0f * I + 1e-6f) / (T + 1e-6f);
        isum += (I + 1e-6f) / (T - I + 1e-6f);
    }
    float dice = 1.0f - dsum / 16.0f;
    float iou  = 1.0f - isum / 16.0f;
    float lv0 = log_vars[0], lv1 = log_vars[1], lv2 = log_vars[2], lv3 = log_vars[3];
    float total = expf(-lv0) * focal + lv0
                + expf(-lv1) * dice  + lv1
                + expf(-lv2) * bnd   + lv2
                + expf(-lv3) * iou   + lv3;
    out[0] = total; out[1] = focal; out[2] = dice; out[3] = bnd; out[4] = iou;
}

extern "C" void kernel_launch(void* const* d_in, const int* in_sizes, int n_in,
                              void* d_out, int out_size) {
    const float* pred     = (const float*)d_in[0];
    const int*   target   = (const int*)d_in[1];
    const float* log_vars = (const float*)d_in[2];
    float* out = (float*)d_out;

    const size_t smem_seeds = 4 * 8192 * sizeof(unsigned);
    const size_t smem_prep  = 8192 * sizeof(unsigned) + 512 * 16 * sizeof(int);
    cudaFuncSetAttribute(k_seeds, cudaFuncAttributeMaxDynamicSharedMemorySize, (int)smem_seeds);
    cudaFuncSetAttribute(k_prep,  cudaFuncAttributeMaxDynamicSharedMemorySize, (int)smem_prep);

    k_zero<<<1, 64>>>();
    k_seeds<<<16, 512, smem_seeds>>>(target);
    k_prep<<<16, 512, smem_prep>>>();
    k_local1<<<16 * NB, 32>>>();
    k_bnd1<<<16, 512>>>();
    k_fix1<<<16 * (NB - 1), 32>>>();
    k_suffix<<<1024, 256>>>();
    k_local2<<<16 * NB, 32>>>();
    k_bnd2<<<16, 512>>>();
    k_fix2<<<16 * (NB - 1), 32>>>();
    k_dmax<<<1024, 256>>>();
    k_losses<<<2048, 256>>>(pred, target);
    k_final<<<1, 32>>>(log_vars, out);
}

// round 9
// speedup vs baseline: 2.2455x; 1.0537x over previous
#include <cuda_runtime.h>
#include <math.h>

#define FULL 0xFFFFFFFFu

#define CH_A 0.955f
#define CH_B 1.3693f
#define CH_INF 1e6f

#define RB 32            // rows per block
#define NB 16            // blocks per image
#define LEV 5            // doubling levels: s = 1..16, then final s = RB

// ---- device scratch (no allocation allowed) ----
__device__ float    g_u[16 * 512 * 512];   // pass-1 tilted rows, then pass-2 tilted rows
__device__ float    g_F[16 * 512 * 512];   // pass-1 seed prefix term
__device__ float    g_S[16 * 512 * 512];   // pass-2 suffix term
__device__ float    g_bnd[16 * NB * 512];  // corrected block-boundary rows
__device__ unsigned g_seed[16 * 8192];     // seed bitboards
__device__ int      g_dmaxb[16];           // per-image max distance (float bits, >=0)
__device__ int      g_hasfg[16];
__device__ float    g_acc[50];

__global__ void k_zero() {
    int i = threadIdx.x;
    if (i < 50) g_acc[i] = 0.0f;
    if (i < 16) g_dmaxb[i] = 0;
}

// ============================================================================
// Seed construction: one CTA per image, 512 threads. int4 loads + redux pack.
// ============================================================================
__global__ void k_seeds(const int* __restrict__ target) {
    extern __shared__ unsigned char smem_raw[];
    unsigned* maskb = (unsigned*)smem_raw;
    unsigned* hdb   = maskb + 8192;
    unsigned* heb   = hdb + 8192;
    unsigned* bdb   = heb + 8192;

    const int img  = blockIdx.x;
    const int tid  = threadIdx.x;
    const int lane = tid & 31;
    const int warp = tid >> 5;
    const int* tg  = target + img * (512 * 512);

    // Phase A: 4 rows per iteration; each thread loads int4 (4 cols).
    const int rowsub  = tid >> 7;            // 0..3
    const int colbase = (warp & 3) * 128;    // warp covers 128 cols
    const int col     = colbase + lane * 4;
    const int grp     = lane >> 3;
    const int sub     = lane & 7;
    const unsigned gm = 0xFFu << (grp * 8);
    unsigned anyfg = 0;
    #pragma unroll 4
    for (int it = 0; it < 128; ++it) {
        int row = it * 4 + rowsub;
        int4 v4 = *(const int4*)(tg + row * 512 + col);
        unsigned nib = (v4.x > 0 ? 1u : 0u) | (v4.y > 0 ? 2u : 0u)
                     | (v4.z > 0 ? 4u : 0u) | (v4.w > 0 ? 8u : 0u);
        anyfg |= nib;
        unsigned word = __reduce_or_sync(gm, nib << (sub * 4));
        if (sub == 0) maskb[row * 16 + (colbase >> 5) + grp] = word;
    }
    int has_fg = __syncthreads_or(anyfg != 0);

    // Phase B: horizontal dilate/erode per word
    #pragma unroll
    for (int k = 0; k < 16; ++k) {
        int i = tid + k * 512;
        int w = i & 15;
        unsigned cw  = maskb[i];
        unsigned pw  = (w > 0)  ? maskb[i - 1] : 0u;
        unsigned nw_ = (w < 15) ? maskb[i + 1] : 0u;
        unsigned ld = (cw << 1) | (pw >> 31);
        unsigned rd = (cw >> 1) | (nw_ << 31);
        hdb[i] = cw | ld | rd;
        unsigned le = (cw << 1) | ((w == 0)  ? 1u          : (pw >> 31));
        unsigned re = (cw >> 1) | ((w == 15) ? 0x80000000u : (nw_ << 31));
        heb[i] = cw & le & re;
    }
    __syncthreads();

    // Phase C: vertical combine -> boundary
    unsigned anyb = 0;
    #pragma unroll
    for (int k = 0; k < 16; ++k) {
        int i = tid + k * 512;
        int r = i >> 4;
        unsigned dil = hdb[i];
        unsigned ero = heb[i];
        if (r > 0)   { dil |= hdb[i - 16]; ero &= heb[i - 16]; }
        if (r < 511) { dil |= hdb[i + 16]; ero &= heb[i + 16]; }
        unsigned bd = dil & ~ero;
        bdb[i] = bd;
        anyb |= bd;
    }
    int has_b = __syncthreads_or(anyb != 0);

    unsigned* gs = g_seed + img * 8192;
    #pragma unroll
    for (int k = 0; k < 16; ++k) {
        int i = tid + k * 512;
        gs[i] = has_b ? bdb[i] : ~maskb[i];
    }
    if (tid == 0) g_hasfg[img] = has_fg;
}

// ============================================================================
// F builder: F[r][j] = -A * (last seeded col <= j in row r), or INF.
// ============================================================================
__global__ void k_prep() {
    extern __shared__ unsigned pm[];
    int* C = (int*)(pm + 8192);
    const int img = blockIdx.x;
    const int tid = threadIdx.x;
    const unsigned* gs = g_seed + img * 8192;

    #pragma unroll
    for (int k = 0; k < 16; ++k) pm[tid + k * 512] = gs[tid + k * 512];
    __syncthreads();

    {
        int cur = -1;
        #pragma unroll
        for (int w = 0; w < 16; ++w) {
            C[tid * 16 + w] = cur;
            unsigned word = pm[tid * 16 + w];
            if (word) cur = w * 32 + 31 - __clz(word);
        }
    }
    __syncthreads();

    float* Fimg = g_F + img * 262144;
    for (int q = tid; q < 65536; q += 512) {
        int idx = q * 4;
        int r = idx >> 9, j0 = idx & 511;
        int w = j0 >> 5;
        unsigned word = pm[r * 16 + w];
        int carry = C[r * 16 + w];
        float4 o;
        #pragma unroll
        for (int e = 0; e < 4; ++e) {
            int j = j0 + e, b = j & 31;
            unsigned lb = word & (0xFFFFFFFFu >> (31 - b));
            int id = lb ? (w * 32 + 31 - __clz(lb)) : carry;
            (&o.x)[e] = (id >= 0) ? (-CH_A * (float)id) : CH_INF;
        }
        *(float4*)(Fimg + idx) = o;
    }
}

static __device__ __forceinline__ void ldrow16(float* d, const float* p) {
    float4 a = *(const float4*)(p);
    float4 b = *(const float4*)(p + 4);
    float4 c = *(const float4*)(p + 8);
    float4 e = *(const float4*)(p + 12);
    d[0]=a.x; d[1]=a.y; d[2]=a.z; d[3]=a.w;
    d[4]=b.x; d[5]=b.y; d[6]=b.z; d[7]=b.w;
    d[8]=c.x; d[9]=c.y; d[10]=c.z; d[11]=c.w;
    d[12]=e.x; d[13]=e.y; d[14]=e.z; d[15]=e.w;
}
static __device__ __forceinline__ void strow16(float* p, const float* d) {
    *(float4*)(p)      = make_float4(d[0], d[1], d[2], d[3]);
    *(float4*)(p + 4)  = make_float4(d[4], d[5], d[6], d[7]);
    *(float4*)(p + 8)  = make_float4(d[8], d[9], d[10], d[11]);
    *(float4*)(p + 12) = make_float4(d[12], d[13], d[14], d[15]);
}

// ============================================================================
// Pass-1 local: 1 warp per (image, block). 32-row recurrence from u=INF.
// 2-row-ahead prefetch of F; barrier-free.
// ============================================================================
__global__ void __launch_bounds__(32, 1) k_local1() {
    const int img = blockIdx.x >> 4, blk = blockIdx.x & 15;
    const int lane = threadIdx.x, c0 = lane * 16;
    const float* Fb = g_F + img * 262144 + blk * RB * 512;
    float* ub = g_u + img * 262144 + blk * RB * 512;

    float u[16], f[16], fn[16], fn2[16], nu[16];
    #pragma unroll
    for (int j = 0; j < 16; ++j) u[j] = CH_INF;
    ldrow16(f,  Fb + c0);
    ldrow16(fn, Fb + 512 + c0);

    for (int r = 0; r < RB; ++r) {
        if (r < RB - 2) ldrow16(fn2, Fb + (r + 2) * 512 + c0);
        float uL = __shfl_up_sync(FULL, u[15], 1); if (lane == 0)  uL = CH_INF;
        float uR = __shfl_down_sync(FULL, u[0], 1); if (lane == 31) uR = CH_INF;
        #pragma unroll
        for (int j = 0; j < 16; ++j) {
            float left  = (j == 0)  ? uL : u[j - 1];
            float right = (j == 15) ? uR : u[j + 1];
            nu[j] = fminf(fminf(u[j] + CH_A, left + (CH_B - CH_A)),
                          fminf(right + (CH_B + CH_A), f[j]));
        }
        strow16(ub + r * 512 + c0, nu);
        #pragma unroll
        for (int j = 0; j < 16; ++j) { u[j] = nu[j]; f[j] = fn[j]; fn[j] = fn2[j]; }
    }
}

// ============================================================================
// Pass-1 boundary: 1 CTA per image, 512 threads; serial over 16 blocks.
// T^RB via LEV doubling steps + final RB step (windowed tilted min).
// ============================================================================
__global__ void k_bnd1() {
    __shared__ float bb[512], wa[512], wb[512], wc[512], wd[512];
    const int img = blockIdx.x;
    const int j = threadIdx.x;
    const float* base = g_u + img * 262144;
    float* gb = g_bnd + img * NB * 512;

    bb[j] = base[(RB - 1) * 512 + j];
    gb[j] = bb[j];
    __syncthreads();

    for (int i = 1; i < NB; ++i) {
        wa[j] = bb[j]; wc[j] = bb[j];
        __syncthreads();
        float *Wr = wa, *Wr2 = wb, *Wl = wc, *Wl2 = wd;
        #pragma unroll
        for (int l = 0; l < LEV; ++l) {
            int s = 1 << l;
            Wr2[j] = fminf(Wr[j], (j >= s)      ? Wr[j - s] + (CH_B - CH_A) * (float)s : CH_INF);
            Wl2[j] = fminf(Wl[j], (j + s < 512) ? Wl[j + s] + (CH_B + CH_A) * (float)s : CH_INF);
            __syncthreads();
            float* t;
            t = Wr; Wr = Wr2; Wr2 = t;
            t = Wl; Wl = Wl2; Wl2 = t;
        }
        float corr = fminf(Wr[j], (j >= RB)       ? bb[j - RB] + (CH_B - CH_A) * (float)RB : CH_INF);
        corr = fminf(corr, fminf(Wl[j], (j + RB < 512) ? bb[j + RB] + (CH_B + CH_A) * (float)RB : CH_INF));
        corr += CH_A * (float)RB;
        float loc = base[(i * RB + RB - 1) * 512 + j];
        float nb = fminf(corr, loc);
        __syncthreads();
        bb[j] = nb;
        gb[i * 512 + j] = nb;
        __syncthreads();
    }
}

// ============================================================================
// Pass-1 fix: 1 warp per (image, block 1..NB-1). v <- T (x) v; merge local.
// ============================================================================
__global__ void __launch_bounds__(32, 1) k_fix1() {
    const int img = blockIdx.x / (NB - 1);
    const int blk = blockIdx.x % (NB - 1) + 1;
    const int lane = threadIdx.x, c0 = lane * 16;
    float* ub = g_u + img * 262144 + blk * RB * 512;

    float v[16], nv[16], loc[16], locn[16], locn2[16];
    ldrow16(v, g_bnd + (img * NB + blk - 1) * 512 + c0);
    ldrow16(loc,  ub + c0);
    ldrow16(locn, ub + 512 + c0);

    for (int r = 0; r < RB; ++r) {
        if (r < RB - 2) ldrow16(locn2, ub + (r + 2) * 512 + c0);
        float vL = __shfl_up_sync(FULL, v[15], 1); if (lane == 0)  vL = CH_INF;
        float vR = __shfl_down_sync(FULL, v[0], 1); if (lane == 31) vR = CH_INF;
        #pragma unroll
        for (int j = 0; j < 16; ++j) {
            float left  = (j == 0)  ? vL : v[j - 1];
            float right = (j == 15) ? vR : v[j + 1];
            nv[j] = fminf(v[j] + CH_A, fminf(left + (CH_B - CH_A), right + (CH_B + CH_A)));
        }
        float out[16];
        #pragma unroll
        for (int j = 0; j < 16; ++j) out[j] = fminf(nv[j], loc[j]);
        strow16(ub + r * 512 + c0, out);
        #pragma unroll
        for (int j = 0; j < 16; ++j) { v[j] = nv[j]; loc[j] = locn[j]; locn[j] = locn2[j]; }
    }
}

// ============================================================================
// Suffix-term builder: S[r][j] = min_{k>=j} (u1[r][k] + A*(2k-511)).
// ============================================================================
__global__ void k_suffix() {
    const int gw   = (blockIdx.x * 256 + threadIdx.x) >> 5;
    const int lane = threadIdx.x & 31;
    const int img  = gw >> 9, row = gw & 511;
    const float* u1 = g_u + img * 262144 + row * 512 + lane * 16;
    float* Sp       = g_S + img * 262144 + row * 512 + lane * 16;

    float nxc[16];
    #pragma unroll
    for (int k = 0; k < 4; ++k) {
        float4 t4 = *(const float4*)(u1 + 4 * k);
        int cb = lane * 16 + 4 * k;
        nxc[4*k]   = t4.x + CH_A * (float)(2 * (cb)     - 511);
        nxc[4*k+1] = t4.y + CH_A * (float)(2 * (cb + 1) - 511);
        nxc[4*k+2] = t4.z + CH_A * (float)(2 * (cb + 2) - 511);
        nxc[4*k+3] = t4.w + CH_A * (float)(2 * (cb + 3) - 511);
    }
    float s[16];
    s[15] = nxc[15];
    #pragma unroll
    for (int j = 14; j >= 0; --j) s[j] = fminf(s[j + 1], nxc[j]);
    float inc = s[0];
    #pragma unroll
    for (int o = 1; o < 32; o <<= 1) {
        float t = __shfl_down_sync(FULL, inc, o);
        if (lane + o < 32) inc = fminf(inc, t);
    }
    float exc = __shfl_down_sync(FULL, inc, 1);
    if (lane == 31) exc = CH_INF;
    #pragma unroll
    for (int k = 0; k < 4; ++k)
        *(float4*)(Sp + 4 * k) = make_float4(fminf(s[4*k], exc), fminf(s[4*k+1], exc),
                                             fminf(s[4*k+2], exc), fminf(s[4*k+3], exc));
}

// ============================================================================
// Pass-2 local (mirrored, bottom->top within block). 2-row prefetch of S.
// ============================================================================
__global__ void __launch_bounds__(32, 1) k_local2() {
    const int img = blockIdx.x >> 4, blk = blockIdx.x & 15;
    const int lane = threadIdx.x, c0 = lane * 16;
    const float* Sb = g_S + img * 262144 + blk * RB * 512;
    float* ub = g_u + img * 262144 + blk * RB * 512;

    float u[16], f[16], fn[16], fn2[16], nu[16];
    #pragma unroll
    for (int j = 0; j < 16; ++j) u[j] = CH_INF;
    ldrow16(f,  Sb + (RB - 1) * 512 + c0);
    ldrow16(fn, Sb + (RB - 2) * 512 + c0);

    for (int r = RB - 1; r >= 0; --r) {
        if (r > 1) ldrow16(fn2, Sb + (r - 2) * 512 + c0);
        float uL = __shfl_up_sync(FULL, u[15], 1); if (lane == 0)  uL = CH_INF;
        float uR = __shfl_down_sync(FULL, u[0], 1); if (lane == 31) uR = CH_INF;
        #pragma unroll
        for (int j = 0; j < 16; ++j) {
            float left  = (j == 0)  ? uL : u[j - 1];
            float right = (j == 15) ? uR : u[j + 1];
            nu[j] = fminf(fminf(u[j] + CH_A, right + (CH_B - CH_A)),
                          fminf(left + (CH_B + CH_A), f[j]));
        }
        strow16(ub + r * 512 + c0, nu);
        #pragma unroll
        for (int j = 0; j < 16; ++j) { u[j] = nu[j]; f[j] = fn[j]; fn[j] = fn2[j]; }
    }
}

// ============================================================================
// Pass-2 boundary (mirrored slopes, blocks bottom-up).
// ============================================================================
__global__ void k_bnd2() {
    __shared__ float bb[512], wa[512], wb[512], wc[512], wd[512];
    const int img = blockIdx.x;
    const int j = threadIdx.x;
    const float* base = g_u + img * 262144;
    float* gb = g_bnd + img * NB * 512;

    bb[j] = base[((NB - 1) * RB) * 512 + j];
    gb[(NB - 1) * 512 + j] = bb[j];
    __syncthreads();

    for (int i = NB - 2; i >= 0; --i) {
        wa[j] = bb[j]; wc[j] = bb[j];
        __syncthreads();
        float *Wr = wa, *Wr2 = wb, *Wl = wc, *Wl2 = wd;
        #pragma unroll
        for (int l = 0; l < LEV; ++l) {
            int s = 1 << l;
            Wr2[j] = fminf(Wr[j], (j + s < 512) ? Wr[j + s] + (CH_B - CH_A) * (float)s : CH_INF);
            Wl2[j] = fminf(Wl[j], (j >= s)      ? Wl[j - s] + (CH_B + CH_A) * (float)s : CH_INF);
            __syncthreads();
            float* t;
            t = Wr; Wr = Wr2; Wr2 = t;
            t = Wl; Wl = Wl2; Wl2 = t;
        }
        float corr = fminf(Wr[j], (j + RB < 512) ? bb[j + RB] + (CH_B - CH_A) * (float)RB : CH_INF);
        corr = fminf(corr, fminf(Wl[j], (j >= RB) ? bb[j - RB] + (CH_B + CH_A) * (float)RB : CH_INF));
        corr += CH_A * (float)RB;
        float loc = base[(i * RB) * 512 + j];
        float nb = fminf(corr, loc);
        __syncthreads();
        bb[j] = nb;
        gb[i * 512 + j] = nb;
        __syncthreads();
    }
}

// ============================================================================
// Pass-2 fix + dmax fold. Grid 16*NB: blk<NB-1 fixes rows (top-down in index),
// blk==NB-1 only computes its max (rows already final).
// ============================================================================
__global__ void __launch_bounds__(32, 1) k_fix2() {
    const int img = blockIdx.x >> 4;
    const int blk = blockIdx.x & 15;
    const int lane = threadIdx.x, c0 = lane * 16;
    float* ub = g_u + img * 262144 + blk * RB * 512;

    float co[16];
    #pragma unroll
    for (int j = 0; j < 16; ++j) co[j] = CH_A * (float)(511 - (c0 + j));

    float dmx = 0.0f;
    if (blk == NB - 1) {
        float rr[16];
        #pragma unroll 4
        for (int r = 0; r < RB; ++r) {
            ldrow16(rr, ub + r * 512 + c0);
            #pragma unroll
            for (int j = 0; j < 16; ++j) dmx = fmaxf(dmx, rr[j] + co[j]);
        }
    } else {
        float v[16], nv[16], loc[16], locn[16], locn2[16];
        ldrow16(v, g_bnd + (img * NB + blk + 1) * 512 + c0);
        ldrow16(loc,  ub + (RB - 1) * 512 + c0);
        ldrow16(locn, ub + (RB - 2) * 512 + c0);

        for (int r = RB - 1; r >= 0; --r) {
            if (r > 1) ldrow16(locn2, ub + (r - 2) * 512 + c0);
            float vL = __shfl_up_sync(FULL, v[15], 1); if (lane == 0)  vL = CH_INF;
            float vR = __shfl_down_sync(FULL, v[0], 1); if (lane == 31) vR = CH_INF;
            #pragma unroll
            for (int j = 0; j < 16; ++j) {
                float left  = (j == 0)  ? vL : v[j - 1];
                float right = (j == 15) ? vR : v[j + 1];
                nv[j] = fminf(v[j] + CH_A, fminf(right + (CH_B - CH_A), left + (CH_B + CH_A)));
            }
            float out[16];
            #pragma unroll
            for (int j = 0; j < 16; ++j) {
                out[j] = fminf(nv[j], loc[j]);
                dmx = fmaxf(dmx, out[j] + co[j]);
            }
            strow16(ub + r * 512 + c0, out);
            #pragma unroll
            for (int j = 0; j < 16; ++j) { v[j] = nv[j]; loc[j] = locn[j]; locn[j] = locn2[j]; }
        }
    }

    #pragma unroll
    for (int o = 16; o >= 1; o >>= 1) dmx = fmaxf(dmx, __shfl_xor_sync(FULL, dmx, o));
    if (lane == 0) atomicMax(&g_dmaxb[img], __float_as_int(dmx));
}

// ============================================================================
// Elementwise losses + reductions (untilts u2 on the fly). Fast math.
// ============================================================================
__global__ void k_losses(const float* __restrict__ pred, const int* __restrict__ target) {
    const int img   = blockIdx.x >> 7;
    const int chunk = blockIdx.x & 127;
    const int base  = img * (512 * 512) + chunk * 2048;
    const int tid   = threadIdx.x;  // 256

    float mx  = __int_as_float(g_dmaxb[img]);
    float inv = (mx > 0.0f) ? (1.0f / fmaxf(mx, 1e-12f)) : 1.0f;
    int hfg   = g_hasfg[img];

    float s_focal = 0.f, s_bnd = 0.f, s_i = 0.f, s_p = 0.f, s_t = 0.f;

    #pragma unroll
    for (int k = 0; k < 2; ++k) {
        int i = base + (k * 256 + tid) * 4;
        float4 x4 = *(const float4*)(pred + i);
        int4   t4 = *(const int4*)(target + i);
        float4 u4 = *(const float4*)(g_u + i);
        int col = i & 511;
        #pragma unroll
        for (int e = 0; e < 4; ++e) {
            float x   = (&x4.x)[e];
            int   tgi = (&t4.x)[e];
            float dd  = (&u4.x)[e] + CH_A * (float)(511 - col - e);
            float t = (float)tgi;
            float ax = fabsf(x);
            float ee = __expf(-ax);
            float l  = __logf(1.0f + ee);
            float lsp = (x >= 0.f) ? -l : (x - l);
            float lsn = (x >= 0.f) ? (-x - l) : -l;
            float bce = -(t * lsp + (1.f - t) * lsn);
            float r1 = __fdividef(1.0f, 1.0f + ee);
            float p = (x >= 0.f) ? r1 : ee * r1;
            float pt = tgi ? p : (1.f - p);
            float at = tgi ? 0.25f : 0.75f;
            float om = 1.f - pt;
            s_focal += at * om * om * bce;
            s_i += p * t;
            s_p += p;
            s_t += t;
            float dn = dd * inv;
            float dist = hfg ? dn : 1.0f;
            s_bnd += (t * (1.f - p) + (1.f - t) * p) * (1.f + dist);
        }
    }

    #pragma unroll
    for (int o = 16; o >= 1; o >>= 1) {
        s_focal += __shfl_xor_sync(FULL, s_focal, o);
        s_bnd   += __shfl_xor_sync(FULL, s_bnd, o);
        s_i     += __shfl_xor_sync(FULL, s_i, o);
        s_p     += __shfl_xor_sync(FULL, s_p, o);
        s_t     += __shfl_xor_sync(FULL, s_t, o);
    }
    __shared__ float red[8][5];
    int lane = tid & 31, wid = tid >> 5;
    if (lane == 0) { red[wid][0]=s_focal; red[wid][1]=s_bnd; red[wid][2]=s_i; red[wid][3]=s_p; red[wid][4]=s_t; }
    __syncthreads();
    if (tid == 0) {
        float a0=0,a1=0,a2=0,a3=0,a4=0;
        #pragma unroll
        for (int k = 0; k < 8; ++k) { a0+=red[k][0]; a1+=red[k][1]; a2+=red[k][2]; a3+=red[k][3]; a4+=red[k][4]; }
        atomicAdd(&g_acc[0], a0);
        atomicAdd(&g_acc[1], a1);
        atomicAdd(&g_acc[2 + img], a2);
        atomicAdd(&g_acc[18 + img], a3);
        atomicAdd(&g_acc[34 + img], a4);
    }
}

// ============================================================================
// Final combine
// ============================================================================
__global__ void k_final(const float* __restrict__ log_vars, float* __restrict__ out) {
    if (threadIdx.x != 0) return;
    const float N = 16.0f * 512.0f * 512.0f;
    float focal = g_acc[0] / N;
    float bnd   = g_acc[1] / N;
    float dsum = 0.f, isum = 0.f;
    #pragma unroll
    for (int b = 0; b < 16; ++b) {
        float I = g_acc[2 + b];
        float T = g_acc[18 + b] + g_acc[34 + b];
        dsum += (2.0f * I + 1e-6f) / (T + 1e-6f);
        isum += (I + 1e-6f) / (T - I + 1e-6f);
    }
    float dice = 1.0f - dsum / 16.0f;
    float iou  = 1.0f - isum / 16.0f;
    float lv0 = log_vars[0], lv1 = log_vars[1], lv2 = log_vars[2], lv3 = log_vars[3];
    float total = expf(-lv0) * focal + lv0
                + expf(-lv1) * dice  + lv1
                + expf(-lv2) * bnd   + lv2
                + expf(-lv3) * iou   + lv3;
    out[0] = total; out[1] = focal; out[2] = dice; out[3] = bnd; out[4] = iou;
}

extern "C" void kernel_launch(void* const* d_in, const int* in_sizes, int n_in,
                              void* d_out, int out_size) {
    const float* pred     = (const float*)d_in[0];
    const int*   target   = (const int*)d_in[1];
    const float* log_vars = (const float*)d_in[2];
    float* out = (float*)d_out;

    const size_t smem_seeds = 4 * 8192 * sizeof(unsigned);
    const size_t smem_prep  = 8192 * sizeof(unsigned) + 512 * 16 * sizeof(int);
    cudaFuncSetAttribute(k_seeds, cudaFuncAttributeMaxDynamicSharedMemorySize, (int)smem_seeds);
    cudaFuncSetAttribute(k_prep,  cudaFuncAttributeMaxDynamicSharedMemorySize, (int)smem_prep);

    k_zero<<<1, 64>>>();
    k_seeds<<<16, 512, smem_seeds>>>(target);
    k_prep<<<16, 512, smem_prep>>>();
    k_local1<<<16 * NB, 32>>>();
    k_bnd1<<<16, 512>>>();
    k_fix1<<<16 * (NB - 1), 32>>>();
    k_suffix<<<1024, 256>>>();
    k_local2<<<16 * NB, 32>>>();
    k_bnd2<<<16, 512>>>();
    k_fix2<<<16 * NB, 32>>>();
    k_losses<<<2048, 256>>>(pred, target);
    k_final<<<1, 32>>>(log_vars, out);
}